// round 11
// baseline (speedup 1.0000x reference)
#include <cuda_runtime.h>
#include <cuda_bf16.h>
#include <cstdint>
#include <math.h>

#define SEQ    2048
#define DMODEL 2048
#define NEGINF (-1e30f)

// ---------------- scratch ----------------
__device__ float g_attn[SEQ * 128];            // affined attention out [S][H*8]
__device__ __nv_bfloat16 g_qh[SEQ * 128];      // tanh(q) hi
__device__ __nv_bfloat16 g_ql[SEQ * 128];      // tanh(q) lo
__device__ __nv_bfloat16 g_kh[SEQ * 32];       // tanh(k) hi
__device__ __nv_bfloat16 g_kl[SEQ * 32];       // tanh(k) lo
__device__ __nv_bfloat16 g_vh[SEQ * 32];       // sigmoid(v) hi
__device__ __nv_bfloat16 g_vl[SEQ * 32];       // sigmoid(v) lo
__device__ __nv_bfloat16 g_xh[SEQ * DMODEL];   // X hi
__device__ __nv_bfloat16 g_xl[SEQ * DMODEL];   // X lo
__device__ __nv_bfloat16 g_wh[192 * DMODEL];   // [Wq;Wk;Wv] hi
__device__ __nv_bfloat16 g_wl[192 * DMODEL];   // [Wq;Wk;Wv] lo

// attn smem layout (float units)
#define QH_OFF    0        // 96 x 16B bf16
#define QL_OFF    384
#define KH_OFF    768      // 2 bufs x 384
#define KL_OFF    1536
#define VTH_OFF   2304     // 2 bufs x [8][72] bf16 (288 fl per buf)
#define VTL_OFF   2880
#define RREC_OFF  3456     // 64: inv_tau/(q+1)
#define MRUN_OFF  3520     // 64
#define LRUN_OFF  3584     // 64
#define FF_OFF    3648     // 64: rescale factor
#define WMAX_OFF  3712     // 2 x 64
#define WSUM_OFF  3840     // 2 x 64
#define OPART_OFF 3968     // 2 x 64 x 8
#define SMEM_FLOATS 4992   // 19968 B

// ---------------- mma helpers ----------------
__device__ __forceinline__ uint32_t smem_u32(const void* p) {
    return (uint32_t)__cvta_generic_to_shared(p);
}
__device__ __forceinline__ void ldsm_x4(uint32_t r[4], uint32_t addr) {
    asm volatile("ldmatrix.sync.aligned.m8n8.x4.shared.b16 {%0,%1,%2,%3}, [%4];"
        : "=r"(r[0]), "=r"(r[1]), "=r"(r[2]), "=r"(r[3]) : "r"(addr));
}
__device__ __forceinline__ void mma_bf16(float c[4], const uint32_t a[4],
                                         uint32_t b0, uint32_t b1) {
    asm volatile("mma.sync.aligned.m16n8k16.row.col.f32.bf16.bf16.f32 "
        "{%0,%1,%2,%3},{%4,%5,%6,%7},{%8,%9},{%0,%1,%2,%3};"
        : "+f"(c[0]), "+f"(c[1]), "+f"(c[2]), "+f"(c[3])
        : "r"(a[0]), "r"(a[1]), "r"(a[2]), "r"(a[3]), "r"(b0), "r"(b1));
}
__device__ __forceinline__ void packpair(float a, float b, uint32_t& hi, uint32_t& lo) {
    __nv_bfloat16 ah = __float2bfloat16(a), bh = __float2bfloat16(b);
    __nv_bfloat16 al = __float2bfloat16(a - __bfloat162float(ah));
    __nv_bfloat16 bl = __float2bfloat16(b - __bfloat162float(bh));
    __nv_bfloat162 H = __halves2bfloat162(ah, bh);
    __nv_bfloat162 L = __halves2bfloat162(al, bl);
    hi = *(uint32_t*)&H; lo = *(uint32_t*)&L;
}

// ---------------- Pass A0: fp32 -> bf16 hi/lo split ----------------
__global__ __launch_bounds__(256) void convert_x(const float* __restrict__ X)
{
    const int i4 = (blockIdx.x * 256 + threadIdx.x) * 4;
    const float4 v = *(const float4*)(X + i4);
    const float xs[4] = {v.x, v.y, v.z, v.w};
    __nv_bfloat16 hs[4], ls[4];
    #pragma unroll
    for (int i = 0; i < 4; ++i) {
        hs[i] = __float2bfloat16(xs[i]);
        ls[i] = __float2bfloat16(xs[i] - __bfloat162float(hs[i]));
    }
    *(uint2*)&g_xh[i4] = *(uint2*)hs;
    *(uint2*)&g_xl[i4] = *(uint2*)ls;
}

__global__ __launch_bounds__(256) void convert_w(
    const float* __restrict__ Wq,
    const float* __restrict__ Wk,
    const float* __restrict__ Wv)
{
    const int i4 = (blockIdx.x * 256 + threadIdx.x) * 4;
    const int n = i4 >> 11, col = i4 & 2047;
    const float* src;
    if (n < 128)      src = Wq + (size_t)n * DMODEL;
    else if (n < 160) src = Wk + (size_t)(n - 128) * DMODEL;
    else              src = Wv + (size_t)(n - 160) * DMODEL;
    const float4 v = *(const float4*)(src + col);
    const float xs[4] = {v.x, v.y, v.z, v.w};
    __nv_bfloat16 hs[4], ls[4];
    #pragma unroll
    for (int i = 0; i < 4; ++i) {
        hs[i] = __float2bfloat16(xs[i]);
        ls[i] = __float2bfloat16(xs[i] - __bfloat162float(hs[i]));
    }
    *(uint2*)&g_wh[i4] = *(uint2*)hs;
    *(uint2*)&g_wl[i4] = *(uint2*)ls;
}

// ---------------- Pass A1: tensor-core QKV projection ----------------
#define PSTR 40
__global__ __launch_bounds__(256) void proj_mma(const float* __restrict__ tau)
{
    __shared__ __nv_bfloat16 sAh[2][64 * PSTR], sAl[2][64 * PSTR];
    __shared__ __nv_bfloat16 sBh[2][64 * PSTR], sBl[2][64 * PSTR];

    const int m0 = blockIdx.x * 64;
    const int n0 = blockIdx.y * 64;
    const int t  = threadIdx.x;
    const int w  = t >> 5, lane = t & 31;
    const int wm = (w & 3) * 16;
    const int wn = (w >> 2) * 32;
    const float inv_tau = 1.0f / tau[0];

    const int lrow = t >> 2;
    const int lcol = (t & 3) * 8;
    const size_t aoff0 = (size_t)(m0 + lrow) * DMODEL + lcol;
    const size_t boff0 = (size_t)(n0 + lrow) * DMODEL + lcol;
    const int sidx = lrow * PSTR + lcol;

    const int seg = lane >> 3, lr8 = lane & 7;
    const int a_r = wm + (seg & 1) * 8 + lr8;
    const int a_c0 = (seg >> 1) * 8;

    float acc[4][4] = {};

    uint4 pah = *(const uint4*)&g_xh[aoff0];
    uint4 pal = *(const uint4*)&g_xl[aoff0];
    uint4 pbh = *(const uint4*)&g_wh[boff0];
    uint4 pbl = *(const uint4*)&g_wl[boff0];

    for (int stage = 0; stage < 64; ++stage) {
        const int buf = stage & 1;
        __syncthreads();
        *(uint4*)&sAh[buf][sidx] = pah;
        *(uint4*)&sAl[buf][sidx] = pal;
        *(uint4*)&sBh[buf][sidx] = pbh;
        *(uint4*)&sBl[buf][sidx] = pbl;
        __syncthreads();
        if (stage + 1 < 64) {
            const size_t koff = (size_t)(stage + 1) * 32;
            pah = *(const uint4*)&g_xh[aoff0 + koff];
            pal = *(const uint4*)&g_xl[aoff0 + koff];
            pbh = *(const uint4*)&g_wh[boff0 + koff];
            pbl = *(const uint4*)&g_wl[boff0 + koff];
        }
        #pragma unroll
        for (int ks = 0; ks < 32; ks += 16) {
            uint32_t ah[4], al[4];
            {
                const int ac = ks + a_c0;
                ldsm_x4(ah, smem_u32(&sAh[buf][a_r * PSTR + ac]));
                ldsm_x4(al, smem_u32(&sAl[buf][a_r * PSTR + ac]));
            }
            #pragma unroll
            for (int nb = 0; nb < 32; nb += 16) {
                const int b_r = wn + nb + (seg >> 1) * 8 + lr8;
                const int b_c = ks + (seg & 1) * 8;
                uint32_t bh[4], bl[4];
                ldsm_x4(bh, smem_u32(&sBh[buf][b_r * PSTR + b_c]));
                ldsm_x4(bl, smem_u32(&sBl[buf][b_r * PSTR + b_c]));
                const int nt = nb >> 3;
                mma_bf16(acc[nt],     ah, bh[0], bh[1]);
                mma_bf16(acc[nt],     ah, bl[0], bl[1]);
                mma_bf16(acc[nt],     al, bh[0], bh[1]);
                mma_bf16(acc[nt + 1], ah, bh[2], bh[3]);
                mma_bf16(acc[nt + 1], ah, bl[2], bl[3]);
                mma_bf16(acc[nt + 1], al, bh[2], bh[3]);
            }
        }
    }

    // epilogue: activations; q/k/v stored as bf16 hi/lo for attn MMA
    const int group = lane >> 2, tg = lane & 3;
    #pragma unroll
    for (int nt = 0; nt < 4; ++nt) {
        const int n = n0 + wn + nt * 8 + tg * 2;
        const int m = m0 + wm + group;
        #pragma unroll
        for (int e = 0; e < 4; ++e) {
            const int mm = m + (e >> 1) * 8;
            const int nn = n + (e & 1);
            const float x = acc[nt][e] * inv_tau;
            if (nn < 160) {
                const float tv = tanhf(x);
                const __nv_bfloat16 th = __float2bfloat16(tv);
                const __nv_bfloat16 tl = __float2bfloat16(tv - __bfloat162float(th));
                if (nn < 128) { g_qh[mm * 128 + nn] = th; g_ql[mm * 128 + nn] = tl; }
                else { g_kh[mm * 32 + (nn - 128)] = th; g_kl[mm * 32 + (nn - 128)] = tl; }
            } else {
                const float sv = 1.0f / (1.0f + expf(-x));
                const __nv_bfloat16 vh = __float2bfloat16(sv);
                const __nv_bfloat16 vl = __float2bfloat16(sv - __bfloat162float(vh));
                g_vh[mm * 32 + (nn - 160)] = vh;
                g_vl[mm * 32 + (nn - 160)] = vl;
            }
        }
    }
}

// ---------------- attn tile loader ----------------
__device__ __forceinline__ void load_kv_tile(float* smem, int k0, int buf, int c, int t)
{
    if (t < 192) {
        const int r = t >> 1, half = t & 1;
        const int gk = k0 - 31 + r;
        uint4 v4 = make_uint4(0u, 0u, 0u, 0u);
        const __nv_bfloat16* src = half ? g_kl : g_kh;
        if (gk >= 0 && gk < SEQ) v4 = *(const uint4*)&src[gk * 32 + c * 8];
        float* dst = smem + (half ? KL_OFF : KH_OFF) + buf * 384;
        *(uint4*)&dst[r * 4] = v4;
    } else {
        const int r = t - 192;            // shifted-v row 0..63
        const int gk = k0 + r + 1;
        uint4 vh4 = make_uint4(0u, 0u, 0u, 0u), vl4 = vh4;
        if (gk < SEQ) {
            vh4 = *(const uint4*)&g_vh[gk * 32 + c * 8];
            vl4 = *(const uint4*)&g_vl[gk * 32 + c * 8];
        }
        __nv_bfloat16* ph = (__nv_bfloat16*)(smem + VTH_OFF + buf * 288);
        __nv_bfloat16* pl = (__nv_bfloat16*)(smem + VTL_OFF + buf * 288);
        const __nv_bfloat16* sh = (const __nv_bfloat16*)&vh4;
        const __nv_bfloat16* sl = (const __nv_bfloat16*)&vl4;
        #pragma unroll
        for (int d = 0; d < 8; ++d) { ph[d * 72 + r] = sh[d]; pl[d * 72 + r] = sl[d]; }
    }
}

// ---------------- Pass B: flash-style suffix attention, all-MMA ----------------
// scores(64x64) = qwin(64x256) . kwin(64x256)^T where win rows are contiguous
// stride-16B slices of the 96-row halo (unfold == flat slice).
__global__ __launch_bounds__(256, 3) void attn_kernel(
    const float* __restrict__ tau,
    const float* __restrict__ ve0,
    const float* __restrict__ ve1)
{
    extern __shared__ float smem[];

    const int h  = blockIdx.y;
    const int qb = 31 - blockIdx.x;
    const int q0 = qb * 64;
    const int c  = h >> 2;
    const int t  = threadIdx.x;
    const int w  = t >> 5, lane = t & 31;
    const int fr = lane >> 2, fq = lane & 3;
    const int seg = lane >> 3, lr8 = lane & 7;
    const int wm = (w & 3) * 16;
    const int wn = (w >> 2) * 32;
    const int wcol = w >> 2;
    const float inv_tau = 1.0f / tau[0];
    const float scale   = 0.0625f * inv_tau;

    // q halo: rows q0-31 .. q0+64, bf16 hi/lo, 16B rows
    if (t < 192) {
        const int r = t >> 1, half = t & 1;
        const int gq = q0 - 31 + r;
        uint4 v4 = make_uint4(0u, 0u, 0u, 0u);
        const __nv_bfloat16* src = half ? g_ql : g_qh;
        if (gq >= 0 && gq < SEQ) v4 = *(const uint4*)&src[gq * 128 + h * 8];
        float* dst = smem + (half ? QL_OFF : QH_OFF);
        *(uint4*)&dst[r * 4] = v4;
    }
    // per-row state init
    if (t < 64) {
        smem[RREC_OFF + t] = inv_tau / (float)(q0 + t + 1);
        smem[MRUN_OFF + t] = NEGINF;
        smem[LRUN_OFF + t] = 0.0f;
    }
    // preload tile 0
    load_kv_tile(smem, 0, 0, c, t);

    // ldmatrix base addresses (bytes). A: m = wm + (seg&1)*8 + lr8, khalf = seg>>1.
    const uint32_t a_off = (uint32_t)((wm + (seg & 1) * 8 + lr8) * 16 + (seg >> 1) * 16);
    const uint32_t aH_b = smem_u32(smem + QH_OFF) + a_off;
    const uint32_t aL_b = smem_u32(smem + QL_OFF) + a_off;
    // B: n = wn + g*16 + (seg>>1)*8 + lr8, khalf = seg&1.
    const uint32_t b_off0 = (uint32_t)((wn + (seg >> 1) * 8 + lr8) * 16 + (seg & 1) * 16);
    const uint32_t kh_base = smem_u32(smem + KH_OFF);
    const uint32_t kl_base = smem_u32(smem + KL_OFF);

    float oacc[4] = {0.f, 0.f, 0.f, 0.f};
    const int r0 = wm + fr, r1 = wm + fr + 8;
    const int qg0 = q0 + r0, qg1 = q0 + r1;

    for (int kb = 0; kb <= qb; ++kb) {
        const int k0 = kb * 64;
        const int buf = kb & 1;
        const bool diag = (kb == qb);
        __syncthreads();                       // bar A

        // ---- scores: 64x64x256 GEMM, hi/lo 3x ----
        const uint32_t bH0 = kh_base + buf * 1536 + b_off0;
        const uint32_t bH1 = bH0 + 256;        // +16 rows * 16B
        const uint32_t bL0 = kl_base + buf * 1536 + b_off0;
        const uint32_t bL1 = bL0 + 256;
        float sacc[4][4] = {};
        #pragma unroll
        for (int j = 0; j < 16; ++j) {
            const uint32_t jo = j * 32;
            uint32_t ah[4], al[4], b0h[4], b1h[4], b0l[4], b1l[4];
            ldsm_x4(ah, aH_b + jo);
            ldsm_x4(al, aL_b + jo);
            ldsm_x4(b0h, bH0 + jo);
            ldsm_x4(b1h, bH1 + jo);
            ldsm_x4(b0l, bL0 + jo);
            ldsm_x4(b1l, bL1 + jo);
            mma_bf16(sacc[0], ah, b0h[0], b0h[1]);
            mma_bf16(sacc[0], ah, b0l[0], b0l[1]);
            mma_bf16(sacc[0], al, b0h[0], b0h[1]);
            mma_bf16(sacc[1], ah, b0h[2], b0h[3]);
            mma_bf16(sacc[1], ah, b0l[2], b0l[3]);
            mma_bf16(sacc[1], al, b0h[2], b0h[3]);
            mma_bf16(sacc[2], ah, b1h[0], b1h[1]);
            mma_bf16(sacc[2], ah, b1l[0], b1l[1]);
            mma_bf16(sacc[2], al, b1h[0], b1h[1]);
            mma_bf16(sacc[3], ah, b1h[2], b1h[3]);
            mma_bf16(sacc[3], ah, b1l[2], b1l[3]);
            mma_bf16(sacc[3], al, b1h[2], b1h[3]);
        }

        // ---- prefetch next tile (overlaps remaining phases) ----
        if (kb < qb) load_kv_tile(smem, k0 + 64, buf ^ 1, c, t);

        // ---- step 4: bias + mask + warp row max ----
        const float br0 = smem[RREC_OFF + r0];
        const float br1 = smem[RREC_OFF + r1];
        float rmax0 = NEGINF, rmax1 = NEGINF;
        #pragma unroll
        for (int nt = 0; nt < 4; ++nt) {
            const int kg = k0 + wn + nt * 8 + 2 * fq;
            float s0 = sacc[nt][0] * scale + (float)kg * br0;
            float s1 = sacc[nt][1] * scale + (float)(kg + 1) * br0;
            float s2 = sacc[nt][2] * scale + (float)kg * br1;
            float s3 = sacc[nt][3] * scale + (float)(kg + 1) * br1;
            if (diag) {
                if (kg >= qg0)     s0 = NEGINF;
                if (kg + 1 >= qg0) s1 = NEGINF;
                if (kg >= qg1)     s2 = NEGINF;
                if (kg + 1 >= qg1) s3 = NEGINF;
            }
            sacc[nt][0] = s0; sacc[nt][1] = s1; sacc[nt][2] = s2; sacc[nt][3] = s3;
            rmax0 = fmaxf(rmax0, fmaxf(s0, s1));
            rmax1 = fmaxf(rmax1, fmaxf(s2, s3));
        }
        rmax0 = fmaxf(rmax0, __shfl_xor_sync(0xffffffffu, rmax0, 1));
        rmax0 = fmaxf(rmax0, __shfl_xor_sync(0xffffffffu, rmax0, 2));
        rmax1 = fmaxf(rmax1, __shfl_xor_sync(0xffffffffu, rmax1, 1));
        rmax1 = fmaxf(rmax1, __shfl_xor_sync(0xffffffffu, rmax1, 2));
        if (fq == 0) {
            smem[WMAX_OFF + wcol * 64 + r0] = rmax0;
            smem[WMAX_OFF + wcol * 64 + r1] = rmax1;
        }
        __syncthreads();                       // bar B

        // ---- step 5: new max + rescale factor ----
        if (t < 64) {
            const float mo = smem[MRUN_OFF + t];
            const float mn = fmaxf(mo, fmaxf(smem[WMAX_OFF + t], smem[WMAX_OFF + 64 + t]));
            smem[FF_OFF + t] = __expf(mo - mn);   // (-1e30)-(-1e30)=0 -> 1 ok
            smem[MRUN_OFF + t] = mn;
        }
        __syncthreads();                       // bar C

        // ---- step 6: e = exp, rescale out, row sums, P.V via MMA ----
        const float mn0 = smem[MRUN_OFF + r0];
        const float mn1 = smem[MRUN_OFF + r1];
        const float f0 = smem[FF_OFF + r0];
        const float f1 = smem[FF_OFF + r1];
        oacc[0] *= f0; oacc[1] *= f0; oacc[2] *= f1; oacc[3] *= f1;
        float sum0 = 0.f, sum1 = 0.f;
        #pragma unroll
        for (int nt = 0; nt < 4; ++nt) {
            float e0 = (sacc[nt][0] > -1e29f) ? __expf(sacc[nt][0] - mn0) : 0.f;
            float e1 = (sacc[nt][1] > -1e29f) ? __expf(sacc[nt][1] - mn0) : 0.f;
            float e2 = (sacc[nt][2] > -1e29f) ? __expf(sacc[nt][2] - mn1) : 0.f;
            float e3 = (sacc[nt][3] > -1e29f) ? __expf(sacc[nt][3] - mn1) : 0.f;
            sacc[nt][0] = e0; sacc[nt][1] = e1; sacc[nt][2] = e2; sacc[nt][3] = e3;
            sum0 += e0 + e1; sum1 += e2 + e3;
        }
        sum0 += __shfl_xor_sync(0xffffffffu, sum0, 1);
        sum0 += __shfl_xor_sync(0xffffffffu, sum0, 2);
        sum1 += __shfl_xor_sync(0xffffffffu, sum1, 1);
        sum1 += __shfl_xor_sync(0xffffffffu, sum1, 2);
        if (fq == 0) {
            smem[WSUM_OFF + wcol * 64 + r0] = sum0;
            smem[WSUM_OFF + wcol * 64 + r1] = sum1;
        }
        // P.V: out(16x8) += e(16x32) . vT(32x8), hi/lo 3x, 2 k16-chunks
        {
            const __nv_bfloat16* vh = (const __nv_bfloat16*)(smem + VTH_OFF + buf * 288);
            const __nv_bfloat16* vl = (const __nv_bfloat16*)(smem + VTL_OFF + buf * 288);
            #pragma unroll
            for (int ch = 0; ch < 2; ++ch) {
                uint32_t eh[4], el[4];
                packpair(sacc[2 * ch][0],     sacc[2 * ch][1],     eh[0], el[0]);
                packpair(sacc[2 * ch][2],     sacc[2 * ch][3],     eh[1], el[1]);
                packpair(sacc[2 * ch + 1][0], sacc[2 * ch + 1][1], eh[2], el[2]);
                packpair(sacc[2 * ch + 1][2], sacc[2 * ch + 1][3], eh[3], el[3]);
                const int kidx = wn + ch * 16 + 2 * fq;
                const uint32_t bh0 = *(const uint32_t*)&vh[fr * 72 + kidx];
                const uint32_t bh1 = *(const uint32_t*)&vh[fr * 72 + kidx + 8];
                const uint32_t bl0 = *(const uint32_t*)&vl[fr * 72 + kidx];
                const uint32_t bl1 = *(const uint32_t*)&vl[fr * 72 + kidx + 8];
                mma_bf16(oacc, eh, bh0, bh1);
                mma_bf16(oacc, eh, bl0, bl1);
                mma_bf16(oacc, el, bh0, bh1);
            }
        }
        __syncthreads();                       // bar D

        // ---- step 7: update l ----
        if (t < 64)
            smem[LRUN_OFF + t] = smem[LRUN_OFF + t] * smem[FF_OFF + t]
                               + smem[WSUM_OFF + t] + smem[WSUM_OFF + 64 + t];
    }

    __syncthreads();
    // out partials to smem
    {
        float* op = smem + OPART_OFF + wcol * 512;
        *(float2*)&op[r0 * 8 + 2 * fq] = make_float2(oacc[0], oacc[1]);
        *(float2*)&op[r1 * 8 + 2 * fq] = make_float2(oacc[2], oacc[3]);
    }
    __syncthreads();
    if (t < 64) {
        const float l = smem[LRUN_OFF + t];
        const float invl = (l > 0.f) ? 1.0f / l : 0.f;
        const int qg = q0 + t;
        #pragma unroll
        for (int d = 0; d < 8; ++d) {
            const float o = (smem[OPART_OFF + t * 8 + d] +
                             smem[OPART_OFF + 512 + t * 8 + d]) * invl;
            const int f = h * 8 + d;
            g_attn[qg * 128 + f] = o * (ve1[f] - ve0[f]) + ve0[f];
        }
    }
}

// ---------------- Pass C: output projection (unchanged) ----------------
__global__ __launch_bounds__(256) void out_kernel(
    const float* __restrict__ Wo,
    float* __restrict__ out)
{
    __shared__ float As[16][132];
    __shared__ float Bs[16][68];
    const int m0 = blockIdx.x * 128;
    const int n0 = blockIdx.y * 64;
    const int t  = threadIdx.x;

    const int arow = t >> 1;
    const int akA  = (t & 1) * 4;
    const int brow = t >> 2;
    const int bk   = (t & 3) * 4;
    const float* ar_ = g_attn + (size_t)(m0 + arow) * 128;
    const float* br_ = Wo + (size_t)(n0 + brow) * 128;

    const int tyy = t >> 4, txx = t & 15;
    const int i0 = tyy * 8, j0 = txx * 4;

    float4 a0 = *(const float4*)(ar_ + akA);
    float4 a1 = *(const float4*)(ar_ + akA + 8);
    float4 b0 = *(const float4*)(br_ + bk);

    float acc[8][4] = {};
    for (int k0 = 0; k0 < 128; k0 += 16) {
        __syncthreads();
        As[akA + 0][arow] = a0.x; As[akA + 1][arow] = a0.y;
        As[akA + 2][arow] = a0.z; As[akA + 3][arow] = a0.w;
        As[akA + 8][arow] = a1.x; As[akA + 9][arow] = a1.y;
        As[akA +10][arow] = a1.z; As[akA +11][arow] = a1.w;
        Bs[bk + 0][brow] = b0.x; Bs[bk + 1][brow] = b0.y;
        Bs[bk + 2][brow] = b0.z; Bs[bk + 3][brow] = b0.w;
        __syncthreads();
        if (k0 + 16 < 128) {
            a0 = *(const float4*)(ar_ + k0 + 16 + akA);
            a1 = *(const float4*)(ar_ + k0 + 16 + akA + 8);
            b0 = *(const float4*)(br_ + k0 + 16 + bk);
        }
        #pragma unroll
        for (int kk = 0; kk < 16; ++kk) {
            const float4 av0 = *(const float4*)&As[kk][i0];
            const float4 av1 = *(const float4*)&As[kk][i0 + 4];
            const float4 bv  = *(const float4*)&Bs[kk][j0];
            float ar[8] = {av0.x, av0.y, av0.z, av0.w, av1.x, av1.y, av1.z, av1.w};
            float br[4] = {bv.x, bv.y, bv.z, bv.w};
            #pragma unroll
            for (int i = 0; i < 8; ++i)
                #pragma unroll
                for (int j = 0; j < 4; ++j)
                    acc[i][j] = fmaf(ar[i], br[j], acc[i][j]);
        }
    }
    #pragma unroll
    for (int i = 0; i < 8; ++i) {
        float4 o = make_float4(acc[i][0], acc[i][1], acc[i][2], acc[i][3]);
        *(float4*)&out[(size_t)(m0 + i0 + i) * DMODEL + n0 + j0] = o;
    }
}

// ---------------- launch ----------------
extern "C" void kernel_launch(void* const* d_in, const int* in_sizes, int n_in,
                              void* d_out, int out_size)
{
    const float* X   = (const float*)d_in[0];
    const float* Wq  = (const float*)d_in[1];
    const float* Wk  = (const float*)d_in[2];
    const float* Wv  = (const float*)d_in[3];
    const float* Wo  = (const float*)d_in[4];
    const float* ve0 = (const float*)d_in[5];
    const float* ve1 = (const float*)d_in[6];
    const float* tau = (const float*)d_in[7];
    float* out = (float*)d_out;
    (void)in_sizes; (void)n_in; (void)out_size;

    cudaFuncSetAttribute(attn_kernel,
                         cudaFuncAttributeMaxDynamicSharedMemorySize,
                         SMEM_FLOATS * (int)sizeof(float));

    convert_x <<<4096, 256>>>(X);
    convert_w <<<384, 256>>>(Wq, Wk, Wv);
    proj_mma  <<<dim3(32, 3), 256>>>(tau);
    attn_kernel<<<dim3(32, 16), 256, SMEM_FLOATS * sizeof(float)>>>(tau, ve0, ve1);
    out_kernel <<<dim3(16, 32), 256>>>(Wo, out);
}

// round 12
// speedup vs baseline: 1.1637x; 1.1637x over previous
#include <cuda_runtime.h>
#include <cuda_bf16.h>
#include <cstdint>
#include <math.h>

#define SEQ    2048
#define DMODEL 2048
#define NEGINF (-1e30f)

// ---------------- scratch ----------------
__device__ __nv_bfloat16 g_oh[SEQ * 128];      // affined attn out hi
__device__ __nv_bfloat16 g_ol[SEQ * 128];      // affined attn out lo
__device__ __nv_bfloat16 g_qh[SEQ * 128];      // tanh(q) hi
__device__ __nv_bfloat16 g_ql[SEQ * 128];      // tanh(q) lo
__device__ __nv_bfloat16 g_kh[SEQ * 32];       // tanh(k) hi
__device__ __nv_bfloat16 g_kl[SEQ * 32];       // tanh(k) lo
__device__ float g_v[SEQ * 32];                // sigmoid(v) fp32
__device__ __nv_bfloat16 g_xh[SEQ * DMODEL];   // X hi
__device__ __nv_bfloat16 g_xl[SEQ * DMODEL];   // X lo
__device__ __nv_bfloat16 g_wh[192 * DMODEL];   // [Wq;Wk;Wv] hi
__device__ __nv_bfloat16 g_wl[192 * DMODEL];   // [Wq;Wk;Wv] lo
__device__ __nv_bfloat16 g_woh[DMODEL * 128];  // Wo hi
__device__ __nv_bfloat16 g_wol[DMODEL * 128];  // Wo lo

// attn smem layout (float units). G row stride 101: prefix lane stride
// 101 == 5 (mod 32) -> conflict-free.
#define GSTR     101
#define QHS_OFF  0                         // 96 x 16B bf16 hi  = 384 fl
#define QLS_OFF  384
#define KHS_OFF  768                       // 2 bufs x 384
#define KLS_OFF  1536
#define VS_OFF   2304                      // 2 x 64 x 8 fp32 = 1024
#define G_OFF    3328
#define SMEM_FLOATS (G_OFF + 96 * GSTR)    // 13024 floats = 52096 B

// ---------------- mma helpers ----------------
__device__ __forceinline__ uint32_t smem_u32(const void* p) {
    return (uint32_t)__cvta_generic_to_shared(p);
}
__device__ __forceinline__ void ldsm_x4(uint32_t r[4], uint32_t addr) {
    asm volatile("ldmatrix.sync.aligned.m8n8.x4.shared.b16 {%0,%1,%2,%3}, [%4];"
        : "=r"(r[0]), "=r"(r[1]), "=r"(r[2]), "=r"(r[3]) : "r"(addr));
}
__device__ __forceinline__ void mma_bf16(float c[4], const uint32_t a[4],
                                         uint32_t b0, uint32_t b1) {
    asm volatile("mma.sync.aligned.m16n8k16.row.col.f32.bf16.bf16.f32 "
        "{%0,%1,%2,%3},{%4,%5,%6,%7},{%8,%9},{%0,%1,%2,%3};"
        : "+f"(c[0]), "+f"(c[1]), "+f"(c[2]), "+f"(c[3])
        : "r"(a[0]), "r"(a[1]), "r"(a[2]), "r"(a[3]), "r"(b0), "r"(b1));
}
__device__ __forceinline__ void mma_k8(float c[4], uint32_t a0, uint32_t a1,
                                       uint32_t b) {
    asm volatile("mma.sync.aligned.m16n8k8.row.col.f32.bf16.bf16.f32 "
        "{%0,%1,%2,%3},{%4,%5},{%6},{%0,%1,%2,%3};"
        : "+f"(c[0]), "+f"(c[1]), "+f"(c[2]), "+f"(c[3])
        : "r"(a0), "r"(a1), "r"(b));
}

// ---------------- converts: fp32 -> bf16 hi/lo ----------------
__global__ __launch_bounds__(256) void convert_x(const float* __restrict__ X)
{
    const int i4 = (blockIdx.x * 256 + threadIdx.x) * 4;
    const float4 v = *(const float4*)(X + i4);
    const float xs[4] = {v.x, v.y, v.z, v.w};
    __nv_bfloat16 hs[4], ls[4];
    #pragma unroll
    for (int i = 0; i < 4; ++i) {
        hs[i] = __float2bfloat16(xs[i]);
        ls[i] = __float2bfloat16(xs[i] - __bfloat162float(hs[i]));
    }
    *(uint2*)&g_xh[i4] = *(uint2*)hs;
    *(uint2*)&g_xl[i4] = *(uint2*)ls;
}

__global__ __launch_bounds__(256) void convert_w(
    const float* __restrict__ Wq,
    const float* __restrict__ Wk,
    const float* __restrict__ Wv)
{
    const int i4 = (blockIdx.x * 256 + threadIdx.x) * 4;
    const int n = i4 >> 11, col = i4 & 2047;
    const float* src;
    if (n < 128)      src = Wq + (size_t)n * DMODEL;
    else if (n < 160) src = Wk + (size_t)(n - 128) * DMODEL;
    else              src = Wv + (size_t)(n - 160) * DMODEL;
    const float4 v = *(const float4*)(src + col);
    const float xs[4] = {v.x, v.y, v.z, v.w};
    __nv_bfloat16 hs[4], ls[4];
    #pragma unroll
    for (int i = 0; i < 4; ++i) {
        hs[i] = __float2bfloat16(xs[i]);
        ls[i] = __float2bfloat16(xs[i] - __bfloat162float(hs[i]));
    }
    *(uint2*)&g_wh[i4] = *(uint2*)hs;
    *(uint2*)&g_wl[i4] = *(uint2*)ls;
}

__global__ __launch_bounds__(256) void convert_wo(const float* __restrict__ Wo)
{
    const int i4 = (blockIdx.x * 256 + threadIdx.x) * 4;   // over 2048*128
    const float4 v = *(const float4*)(Wo + i4);
    const float xs[4] = {v.x, v.y, v.z, v.w};
    __nv_bfloat16 hs[4], ls[4];
    #pragma unroll
    for (int i = 0; i < 4; ++i) {
        hs[i] = __float2bfloat16(xs[i]);
        ls[i] = __float2bfloat16(xs[i] - __bfloat162float(hs[i]));
    }
    *(uint2*)&g_woh[i4] = *(uint2*)hs;
    *(uint2*)&g_wol[i4] = *(uint2*)ls;
}

// ---------------- Pass A: tensor-core QKV projection ----------------
#define PSTR 40
__global__ __launch_bounds__(256) void proj_mma(const float* __restrict__ tau)
{
    __shared__ __nv_bfloat16 sAh[2][64 * PSTR], sAl[2][64 * PSTR];
    __shared__ __nv_bfloat16 sBh[2][64 * PSTR], sBl[2][64 * PSTR];

    const int m0 = blockIdx.x * 64;
    const int n0 = blockIdx.y * 64;
    const int t  = threadIdx.x;
    const int w  = t >> 5, lane = t & 31;
    const int wm = (w & 3) * 16;
    const int wn = (w >> 2) * 32;
    const float inv_tau = 1.0f / tau[0];

    const int lrow = t >> 2;
    const int lcol = (t & 3) * 8;
    const size_t aoff0 = (size_t)(m0 + lrow) * DMODEL + lcol;
    const size_t boff0 = (size_t)(n0 + lrow) * DMODEL + lcol;
    const int sidx = lrow * PSTR + lcol;

    const int seg = lane >> 3, lr8 = lane & 7;
    const int a_r = wm + (seg & 1) * 8 + lr8;
    const int a_c0 = (seg >> 1) * 8;

    float acc[4][4] = {};

    uint4 pah = *(const uint4*)&g_xh[aoff0];
    uint4 pal = *(const uint4*)&g_xl[aoff0];
    uint4 pbh = *(const uint4*)&g_wh[boff0];
    uint4 pbl = *(const uint4*)&g_wl[boff0];

    for (int stage = 0; stage < 64; ++stage) {
        const int buf = stage & 1;
        __syncthreads();
        *(uint4*)&sAh[buf][sidx] = pah;
        *(uint4*)&sAl[buf][sidx] = pal;
        *(uint4*)&sBh[buf][sidx] = pbh;
        *(uint4*)&sBl[buf][sidx] = pbl;
        __syncthreads();
        if (stage + 1 < 64) {
            const size_t koff = (size_t)(stage + 1) * 32;
            pah = *(const uint4*)&g_xh[aoff0 + koff];
            pal = *(const uint4*)&g_xl[aoff0 + koff];
            pbh = *(const uint4*)&g_wh[boff0 + koff];
            pbl = *(const uint4*)&g_wl[boff0 + koff];
        }
        #pragma unroll
        for (int ks = 0; ks < 32; ks += 16) {
            uint32_t ah[4], al[4];
            {
                const int ac = ks + a_c0;
                ldsm_x4(ah, smem_u32(&sAh[buf][a_r * PSTR + ac]));
                ldsm_x4(al, smem_u32(&sAl[buf][a_r * PSTR + ac]));
            }
            #pragma unroll
            for (int nb = 0; nb < 32; nb += 16) {
                const int b_r = wn + nb + (seg >> 1) * 8 + lr8;
                const int b_c = ks + (seg & 1) * 8;
                uint32_t bh[4], bl[4];
                ldsm_x4(bh, smem_u32(&sBh[buf][b_r * PSTR + b_c]));
                ldsm_x4(bl, smem_u32(&sBl[buf][b_r * PSTR + b_c]));
                const int nt = nb >> 3;
                mma_bf16(acc[nt],     ah, bh[0], bh[1]);
                mma_bf16(acc[nt],     ah, bl[0], bl[1]);
                mma_bf16(acc[nt],     al, bh[0], bh[1]);
                mma_bf16(acc[nt + 1], ah, bh[2], bh[3]);
                mma_bf16(acc[nt + 1], ah, bl[2], bl[3]);
                mma_bf16(acc[nt + 1], al, bh[2], bh[3]);
            }
        }
    }

    // epilogue: activations; q/k bf16 hi/lo, v fp32
    const int group = lane >> 2, tg = lane & 3;
    #pragma unroll
    for (int nt = 0; nt < 4; ++nt) {
        const int n = n0 + wn + nt * 8 + tg * 2;
        const int m = m0 + wm + group;
        #pragma unroll
        for (int e = 0; e < 4; ++e) {
            const int mm = m + (e >> 1) * 8;
            const int nn = n + (e & 1);
            const float x = acc[nt][e] * inv_tau;
            if (nn < 160) {
                const float tv = tanhf(x);
                const __nv_bfloat16 th = __float2bfloat16(tv);
                const __nv_bfloat16 tl = __float2bfloat16(tv - __bfloat162float(th));
                if (nn < 128) { g_qh[mm * 128 + nn] = th; g_ql[mm * 128 + nn] = tl; }
                else { g_kh[mm * 32 + (nn - 128)] = th; g_kl[mm * 32 + (nn - 128)] = tl; }
            } else {
                g_v[mm * 32 + (nn - 160)] = 1.0f / (1.0f + expf(-x));
            }
        }
    }
}

// ---------------- Pass B: suffix attention (MMA G + prefix; no-max softmax) ----------------
__global__ __launch_bounds__(256, 3) void attn_kernel(
    const float* __restrict__ tau,
    const float* __restrict__ ve0,
    const float* __restrict__ ve1)
{
    extern __shared__ float smem[];
    const uint32_t* qh32 = (const uint32_t*)(smem + QHS_OFF);
    const uint32_t* ql32 = (const uint32_t*)(smem + QLS_OFF);
    float* vsb = smem + VS_OFF;
    float* G   = smem + G_OFF;

    const int h  = blockIdx.y;
    const int qb = 31 - blockIdx.x;
    const int q0 = qb * 64;
    const int c  = h >> 2;
    const int t  = threadIdx.x;
    const int w  = t >> 5, lane = t & 31;
    const float inv_tau = 1.0f / tau[0];
    const float scale   = 0.0625f * inv_tau;

    // q halo
    if (t < 192) {
        const int r = t >> 1, half = t & 1;
        const int gq = q0 - 31 + r;
        uint4 v4 = make_uint4(0u, 0u, 0u, 0u);
        const __nv_bfloat16* src = half ? g_ql : g_qh;
        if (gq >= 0 && gq < SEQ) v4 = *(const uint4*)&src[gq * 128 + h * 8];
        float* dst = smem + (half ? QLS_OFF : QHS_OFF);
        *(uint4*)&dst[r * 4] = v4;
    }

    const int a  = t >> 2;
    const int jq = t & 3;
    const int qg = q0 + a;
    const float bias_r = inv_tau / (float)(qg + 1);

    float l_run = 0.0f;
    float acc[8];
    #pragma unroll
    for (int d = 0; d < 8; ++d) acc[d] = 0.0f;

    const int fr = lane >> 2, fq = lane & 3;
    const int fc = fq * 2;

    const int lr = t >> 1, lhalf = t & 1;
    const int lu = t - 192;

    // preload tile 0
    {
        if (t < 192) {
            const int gk = -31 + lr;
            uint4 v4 = make_uint4(0u, 0u, 0u, 0u);
            const __nv_bfloat16* src = lhalf ? g_kl : g_kh;
            if (gk >= 0) v4 = *(const uint4*)&src[gk * 32 + c * 8];
            float* dst = smem + (lhalf ? KLS_OFF : KHS_OFF);
            *(uint4*)&dst[lr * 4] = v4;
        } else {
            #pragma unroll
            for (int rep = 0; rep < 2; ++rep) {
                const int idx = lu * 2 + rep;
                const int r = idx >> 1, half = idx & 1;
                const int gk = r + 1;
                float4 v4 = *(const float4*)&g_v[gk * 32 + c * 8 + half * 4];
                *(float4*)&vsb[r * 8 + half * 4] = v4;
            }
        }
    }

    for (int kb = 0; kb <= qb; ++kb) {
        const int k0 = kb * 64;
        const int buf = kb & 1;
        const uint32_t* kh32 = (const uint32_t*)(smem + KHS_OFF + buf * 384);
        const uint32_t* kl32 = (const uint32_t*)(smem + KLS_OFF + buf * 384);
        const float* vsm = vsb + buf * 512;
        __syncthreads();

        // ---- G via m16n8k8, hi/lo 3x ----
        #pragma unroll
        for (int k9 = 0; k9 < 9; ++k9) {
            const int p  = w + (k9 << 3);
            const int mt = p / 12;
            const int nt = p - mt * 12;
            const int ai = (mt * 16 + fr) * 4 + fq;
            const uint32_t ah0 = qh32[ai],      ah1 = qh32[ai + 32];
            const uint32_t al0 = ql32[ai],      al1 = ql32[ai + 32];
            const int bi = (nt * 8 + fr) * 4 + fq;
            const uint32_t bh = kh32[bi], bl = kl32[bi];
            float cfr[4] = {0.f, 0.f, 0.f, 0.f};
            mma_k8(cfr, ah0, ah1, bh);
            mma_k8(cfr, ah0, ah1, bl);
            mma_k8(cfr, al0, al1, bh);
            float* gp = &G[(mt * 16 + fr) * GSTR + nt * 8 + fc];
            gp[0] = cfr[0]; gp[1] = cfr[1];
            gp[8 * GSTR] = cfr[2]; gp[8 * GSTR + 1] = cfr[3];
        }
        __syncthreads();

        // ---- diagonal prefix; v-prefetch on spare threads ----
        if (t < 191) {
            const int dlt = t - 95;
            const int ad  = dlt < 0 ? -dlt : dlt;
            const int L   = 96 - ad;
            int off = (dlt > 0) ? dlt * GSTR : -dlt;
            float carry = 0.0f;
            int s = 0;
            for (; s + 4 <= L; s += 4) {
                const float e0 = G[off];
                const float e1 = G[off + (GSTR + 1)];
                const float e2 = G[off + 2 * (GSTR + 1)];
                const float e3 = G[off + 3 * (GSTR + 1)];
                const float c0 = carry + e0;
                const float c1 = c0 + e1;
                const float c2 = c1 + e2;
                const float c3 = c2 + e3;
                G[off] = c0;
                G[off + (GSTR + 1)]     = c1;
                G[off + 2 * (GSTR + 1)] = c2;
                G[off + 3 * (GSTR + 1)] = c3;
                carry = c3;
                off += 4 * (GSTR + 1);
            }
            for (; s < L; ++s) { carry += G[off]; G[off] = carry; off += GSTR + 1; }
        } else if (t >= 192 && kb < qb) {
            const int nk0 = k0 + 64;
            #pragma unroll
            for (int rep = 0; rep < 2; ++rep) {
                const int idx = lu * 2 + rep;
                const int r = idx >> 1, half = idx & 1;
                const int gk = nk0 + r + 1;
                float4 v4 = make_float4(0.f, 0.f, 0.f, 0.f);
                if (gk < SEQ) v4 = *(const float4*)&g_v[gk * 32 + c * 8 + half * 4];
                *(float4*)&vsb[(buf ^ 1) * 512 + r * 8 + half * 4] = v4;
            }
        }
        __syncthreads();

        // ---- k-halo prefetch for next tile ----
        if (kb < qb && t < 192) {
            const int gk = k0 + 64 - 31 + lr;
            const __nv_bfloat16* src = lhalf ? g_kl : g_kh;
            const uint4 v4 = *(const uint4*)&src[gk * 32 + c * 8];
            float* dst = smem + (lhalf ? KLS_OFF : KHS_OFF) + (buf ^ 1) * 384;
            *(uint4*)&dst[lr * 4] = v4;
        }

        // ---- scores + no-max softmax accumulation ----
        // scores bounded (<17) so exp never overflows; skip max tracking.
        const int browH = (a + 31) * GSTR + 31;
        const int browL = (a - 1) * GSTR - 1;
        #pragma unroll
        for (int bb = 0; bb < 16; ++bb) {
            const int b  = (bb << 2) | jq;
            const int kg = k0 + b;
            if (kg < qg) {
                const float hi = G[browH + b];
                const float lo = (a > 0 && b > 0) ? G[browL + b] : 0.0f;
                const float s = (hi - lo) * scale + (float)kg * bias_r;
                const float e = __expf(s);
                l_run += e;
                const float4 v0 = *(const float4*)&vsm[b * 8];
                const float4 v1 = *(const float4*)&vsm[b * 8 + 4];
                acc[0] = fmaf(e, v0.x, acc[0]); acc[1] = fmaf(e, v0.y, acc[1]);
                acc[2] = fmaf(e, v0.z, acc[2]); acc[3] = fmaf(e, v0.w, acc[3]);
                acc[4] = fmaf(e, v1.x, acc[4]); acc[5] = fmaf(e, v1.y, acc[5]);
                acc[6] = fmaf(e, v1.z, acc[6]); acc[7] = fmaf(e, v1.w, acc[7]);
            }
        }
    }

    // sum-merge the 4 threads of each query row
    #pragma unroll
    for (int off = 1; off < 4; off <<= 1) {
        l_run += __shfl_xor_sync(0xffffffffu, l_run, off);
        #pragma unroll
        for (int d = 0; d < 8; ++d)
            acc[d] += __shfl_xor_sync(0xffffffffu, acc[d], off);
    }
    if (jq == 0) {
        const float invl = (l_run > 0.0f) ? 1.0f / l_run : 0.0f;
        #pragma unroll
        for (int d = 0; d < 8; ++d) {
            const int f = h * 8 + d;
            const float e0 = ve0[f], e1 = ve1[f];
            const float o  = acc[d] * invl;
            const float fin = o * (e1 - e0) + e0;
            const __nv_bfloat16 fh = __float2bfloat16(fin);
            const __nv_bfloat16 fl = __float2bfloat16(fin - __bfloat162float(fh));
            g_oh[qg * 128 + f] = fh;
            g_ol[qg * 128 + f] = fl;
        }
    }
}

// ---------------- Pass C: output projection via MMA (K=128) ----------------
__global__ __launch_bounds__(256) void out_mma(float* __restrict__ out)
{
    __shared__ __nv_bfloat16 sAh[2][64 * PSTR], sAl[2][64 * PSTR];
    __shared__ __nv_bfloat16 sBh[2][64 * PSTR], sBl[2][64 * PSTR];

    const int m0 = blockIdx.x * 64;
    const int n0 = blockIdx.y * 64;
    const int t  = threadIdx.x;
    const int w  = t >> 5, lane = t & 31;
    const int wm = (w & 3) * 16;
    const int wn = (w >> 2) * 32;

    const int lrow = t >> 2;
    const int lcol = (t & 3) * 8;
    const size_t aoff0 = (size_t)(m0 + lrow) * 128 + lcol;
    const size_t boff0 = (size_t)(n0 + lrow) * 128 + lcol;
    const int sidx = lrow * PSTR + lcol;

    const int seg = lane >> 3, lr8 = lane & 7;
    const int a_r = wm + (seg & 1) * 8 + lr8;
    const int a_c0 = (seg >> 1) * 8;

    float acc[4][4] = {};

    uint4 pah = *(const uint4*)&g_oh[aoff0];
    uint4 pal = *(const uint4*)&g_ol[aoff0];
    uint4 pbh = *(const uint4*)&g_woh[boff0];
    uint4 pbl = *(const uint4*)&g_wol[boff0];

    for (int stage = 0; stage < 4; ++stage) {
        const int buf = stage & 1;
        __syncthreads();
        *(uint4*)&sAh[buf][sidx] = pah;
        *(uint4*)&sAl[buf][sidx] = pal;
        *(uint4*)&sBh[buf][sidx] = pbh;
        *(uint4*)&sBl[buf][sidx] = pbl;
        __syncthreads();
        if (stage + 1 < 4) {
            const size_t koff = (size_t)(stage + 1) * 32;
            pah = *(const uint4*)&g_oh[aoff0 + koff];
            pal = *(const uint4*)&g_ol[aoff0 + koff];
            pbh = *(const uint4*)&g_woh[boff0 + koff];
            pbl = *(const uint4*)&g_wol[boff0 + koff];
        }
        #pragma unroll
        for (int ks = 0; ks < 32; ks += 16) {
            uint32_t ah[4], al[4];
            {
                const int ac = ks + a_c0;
                ldsm_x4(ah, smem_u32(&sAh[buf][a_r * PSTR + ac]));
                ldsm_x4(al, smem_u32(&sAl[buf][a_r * PSTR + ac]));
            }
            #pragma unroll
            for (int nb = 0; nb < 32; nb += 16) {
                const int b_r = wn + nb + (seg >> 1) * 8 + lr8;
                const int b_c = ks + (seg & 1) * 8;
                uint32_t bh[4], bl[4];
                ldsm_x4(bh, smem_u32(&sBh[buf][b_r * PSTR + b_c]));
                ldsm_x4(bl, smem_u32(&sBl[buf][b_r * PSTR + b_c]));
                const int nt = nb >> 3;
                mma_bf16(acc[nt],     ah, bh[0], bh[1]);
                mma_bf16(acc[nt],     ah, bl[0], bl[1]);
                mma_bf16(acc[nt],     al, bh[0], bh[1]);
                mma_bf16(acc[nt + 1], ah, bh[2], bh[3]);
                mma_bf16(acc[nt + 1], ah, bl[2], bl[3]);
                mma_bf16(acc[nt + 1], al, bh[2], bh[3]);
            }
        }
    }

    const int group = lane >> 2, tg = lane & 3;
    #pragma unroll
    for (int nt = 0; nt < 4; ++nt) {
        const int n = n0 + wn + nt * 8 + tg * 2;
        const int m = m0 + wm + group;
        #pragma unroll
        for (int e = 0; e < 4; ++e) {
            const int mm = m + (e >> 1) * 8;
            const int nn = n + (e & 1);
            out[(size_t)mm * DMODEL + nn] = acc[nt][e];
        }
    }
}

// ---------------- launch ----------------
extern "C" void kernel_launch(void* const* d_in, const int* in_sizes, int n_in,
                              void* d_out, int out_size)
{
    const float* X   = (const float*)d_in[0];
    const float* Wq  = (const float*)d_in[1];
    const float* Wk  = (const float*)d_in[2];
    const float* Wv  = (const float*)d_in[3];
    const float* Wo  = (const float*)d_in[4];
    const float* ve0 = (const float*)d_in[5];
    const float* ve1 = (const float*)d_in[6];
    const float* tau = (const float*)d_in[7];
    float* out = (float*)d_out;
    (void)in_sizes; (void)n_in; (void)out_size;

    cudaFuncSetAttribute(attn_kernel,
                         cudaFuncAttributeMaxDynamicSharedMemorySize,
                         SMEM_FLOATS * (int)sizeof(float));

    convert_x <<<4096, 256>>>(X);
    convert_w <<<384, 256>>>(Wq, Wk, Wv);
    convert_wo<<<256, 256>>>(Wo);
    proj_mma  <<<dim3(32, 3), 256>>>(tau);
    attn_kernel<<<dim3(32, 16), 256, SMEM_FLOATS * sizeof(float)>>>(tau, ve0, ve1);
    out_mma   <<<dim3(32, 32), 256>>>(out);
}

// round 13
// speedup vs baseline: 1.2398x; 1.0654x over previous
#include <cuda_runtime.h>
#include <cuda_bf16.h>
#include <cstdint>
#include <math.h>

#define SEQ    2048
#define DMODEL 2048
#define NEGINF (-1e30f)

// ---------------- scratch ----------------
__device__ __nv_bfloat16 g_oh[SEQ * 128];      // affined attn out hi
__device__ __nv_bfloat16 g_ol[SEQ * 128];      // affined attn out lo
__device__ __nv_bfloat16 g_qh[SEQ * 128];      // tanh(q) hi
__device__ __nv_bfloat16 g_ql[SEQ * 128];      // tanh(q) lo
__device__ __nv_bfloat16 g_kh[SEQ * 32];       // tanh(k) hi
__device__ __nv_bfloat16 g_kl[SEQ * 32];       // tanh(k) lo
__device__ float g_v[SEQ * 32];                // sigmoid(v) fp32
__device__ __nv_bfloat16 g_xh[SEQ * DMODEL];   // X hi
__device__ __nv_bfloat16 g_xl[SEQ * DMODEL];   // X lo
__device__ __nv_bfloat16 g_wh[192 * DMODEL];   // [Wq;Wk;Wv] hi
__device__ __nv_bfloat16 g_wl[192 * DMODEL];   // [Wq;Wk;Wv] lo
__device__ __nv_bfloat16 g_woh[DMODEL * 128];  // Wo hi
__device__ __nv_bfloat16 g_wol[DMODEL * 128];  // Wo lo
__device__ float g_part[4 * SEQ * 192];        // proj split-K partials

// attn smem layout (float units). G row stride 101: prefix lane stride
// 101 == 5 (mod 32) -> conflict-free.
#define GSTR     101
#define QHS_OFF  0                         // 96 x 16B bf16 hi  = 384 fl
#define QLS_OFF  384
#define KHS_OFF  768                       // 2 bufs x 384
#define KLS_OFF  1536
#define VS_OFF   2304                      // 2 x 64 x 8 fp32 = 1024
#define G_OFF    3328
#define SMEM_FLOATS (G_OFF + 96 * GSTR)    // 13024 floats = 52096 B

// ---------------- mma helpers ----------------
__device__ __forceinline__ uint32_t smem_u32(const void* p) {
    return (uint32_t)__cvta_generic_to_shared(p);
}
__device__ __forceinline__ void ldsm_x4(uint32_t r[4], uint32_t addr) {
    asm volatile("ldmatrix.sync.aligned.m8n8.x4.shared.b16 {%0,%1,%2,%3}, [%4];"
        : "=r"(r[0]), "=r"(r[1]), "=r"(r[2]), "=r"(r[3]) : "r"(addr));
}
__device__ __forceinline__ void mma_bf16(float c[4], const uint32_t a[4],
                                         uint32_t b0, uint32_t b1) {
    asm volatile("mma.sync.aligned.m16n8k16.row.col.f32.bf16.bf16.f32 "
        "{%0,%1,%2,%3},{%4,%5,%6,%7},{%8,%9},{%0,%1,%2,%3};"
        : "+f"(c[0]), "+f"(c[1]), "+f"(c[2]), "+f"(c[3])
        : "r"(a[0]), "r"(a[1]), "r"(a[2]), "r"(a[3]), "r"(b0), "r"(b1));
}
__device__ __forceinline__ void mma_k8(float c[4], uint32_t a0, uint32_t a1,
                                       uint32_t b) {
    asm volatile("mma.sync.aligned.m16n8k8.row.col.f32.bf16.bf16.f32 "
        "{%0,%1,%2,%3},{%4,%5},{%6},{%0,%1,%2,%3};"
        : "+f"(c[0]), "+f"(c[1]), "+f"(c[2]), "+f"(c[3])
        : "r"(a0), "r"(a1), "r"(b));
}

// ---------------- converts: fp32 -> bf16 hi/lo ----------------
__global__ __launch_bounds__(256) void convert_x(const float* __restrict__ X)
{
    const int i4 = (blockIdx.x * 256 + threadIdx.x) * 4;
    const float4 v = *(const float4*)(X + i4);
    const float xs[4] = {v.x, v.y, v.z, v.w};
    __nv_bfloat16 hs[4], ls[4];
    #pragma unroll
    for (int i = 0; i < 4; ++i) {
        hs[i] = __float2bfloat16(xs[i]);
        ls[i] = __float2bfloat16(xs[i] - __bfloat162float(hs[i]));
    }
    *(uint2*)&g_xh[i4] = *(uint2*)hs;
    *(uint2*)&g_xl[i4] = *(uint2*)ls;
}

__global__ __launch_bounds__(256) void convert_w(
    const float* __restrict__ Wq,
    const float* __restrict__ Wk,
    const float* __restrict__ Wv)
{
    const int i4 = (blockIdx.x * 256 + threadIdx.x) * 4;
    const int n = i4 >> 11, col = i4 & 2047;
    const float* src;
    if (n < 128)      src = Wq + (size_t)n * DMODEL;
    else if (n < 160) src = Wk + (size_t)(n - 128) * DMODEL;
    else              src = Wv + (size_t)(n - 160) * DMODEL;
    const float4 v = *(const float4*)(src + col);
    const float xs[4] = {v.x, v.y, v.z, v.w};
    __nv_bfloat16 hs[4], ls[4];
    #pragma unroll
    for (int i = 0; i < 4; ++i) {
        hs[i] = __float2bfloat16(xs[i]);
        ls[i] = __float2bfloat16(xs[i] - __bfloat162float(hs[i]));
    }
    *(uint2*)&g_wh[i4] = *(uint2*)hs;
    *(uint2*)&g_wl[i4] = *(uint2*)ls;
}

__global__ __launch_bounds__(256) void convert_wo(const float* __restrict__ Wo)
{
    const int i4 = (blockIdx.x * 256 + threadIdx.x) * 4;   // over 2048*128
    const float4 v = *(const float4*)(Wo + i4);
    const float xs[4] = {v.x, v.y, v.z, v.w};
    __nv_bfloat16 hs[4], ls[4];
    #pragma unroll
    for (int i = 0; i < 4; ++i) {
        hs[i] = __float2bfloat16(xs[i]);
        ls[i] = __float2bfloat16(xs[i] - __bfloat162float(hs[i]));
    }
    *(uint2*)&g_woh[i4] = *(uint2*)hs;
    *(uint2*)&g_wol[i4] = *(uint2*)ls;
}

// ---------------- Pass A1: split-K tensor-core QKV projection ----------------
// grid (32, 3, 4): kz chunk of K=512 (16 stages). fp32 partials to g_part.
#define PSTR 40
__global__ __launch_bounds__(256) void proj_mma()
{
    __shared__ __nv_bfloat16 sAh[2][64 * PSTR], sAl[2][64 * PSTR];
    __shared__ __nv_bfloat16 sBh[2][64 * PSTR], sBl[2][64 * PSTR];

    const int m0 = blockIdx.x * 64;
    const int n0 = blockIdx.y * 64;
    const int kz = blockIdx.z;
    const size_t kbase = (size_t)kz * 512;
    const int t  = threadIdx.x;
    const int w  = t >> 5, lane = t & 31;
    const int wm = (w & 3) * 16;
    const int wn = (w >> 2) * 32;

    const int lrow = t >> 2;
    const int lcol = (t & 3) * 8;
    const size_t aoff0 = (size_t)(m0 + lrow) * DMODEL + kbase + lcol;
    const size_t boff0 = (size_t)(n0 + lrow) * DMODEL + kbase + lcol;
    const int sidx = lrow * PSTR + lcol;

    const int seg = lane >> 3, lr8 = lane & 7;
    const int a_r = wm + (seg & 1) * 8 + lr8;
    const int a_c0 = (seg >> 1) * 8;

    float acc[4][4] = {};

    uint4 pah = *(const uint4*)&g_xh[aoff0];
    uint4 pal = *(const uint4*)&g_xl[aoff0];
    uint4 pbh = *(const uint4*)&g_wh[boff0];
    uint4 pbl = *(const uint4*)&g_wl[boff0];

    for (int stage = 0; stage < 16; ++stage) {
        const int buf = stage & 1;
        __syncthreads();
        *(uint4*)&sAh[buf][sidx] = pah;
        *(uint4*)&sAl[buf][sidx] = pal;
        *(uint4*)&sBh[buf][sidx] = pbh;
        *(uint4*)&sBl[buf][sidx] = pbl;
        __syncthreads();
        if (stage + 1 < 16) {
            const size_t koff = (size_t)(stage + 1) * 32;
            pah = *(const uint4*)&g_xh[aoff0 + koff];
            pal = *(const uint4*)&g_xl[aoff0 + koff];
            pbh = *(const uint4*)&g_wh[boff0 + koff];
            pbl = *(const uint4*)&g_wl[boff0 + koff];
        }
        #pragma unroll
        for (int ks = 0; ks < 32; ks += 16) {
            uint32_t ah[4], al[4];
            {
                const int ac = ks + a_c0;
                ldsm_x4(ah, smem_u32(&sAh[buf][a_r * PSTR + ac]));
                ldsm_x4(al, smem_u32(&sAl[buf][a_r * PSTR + ac]));
            }
            #pragma unroll
            for (int nb = 0; nb < 32; nb += 16) {
                const int b_r = wn + nb + (seg >> 1) * 8 + lr8;
                const int b_c = ks + (seg & 1) * 8;
                uint32_t bh[4], bl[4];
                ldsm_x4(bh, smem_u32(&sBh[buf][b_r * PSTR + b_c]));
                ldsm_x4(bl, smem_u32(&sBl[buf][b_r * PSTR + b_c]));
                const int nt = nb >> 3;
                mma_bf16(acc[nt],     ah, bh[0], bh[1]);
                mma_bf16(acc[nt],     ah, bl[0], bl[1]);
                mma_bf16(acc[nt],     al, bh[0], bh[1]);
                mma_bf16(acc[nt + 1], ah, bh[2], bh[3]);
                mma_bf16(acc[nt + 1], ah, bl[2], bl[3]);
                mma_bf16(acc[nt + 1], al, bh[2], bh[3]);
            }
        }
    }

    // write fp32 partials
    const int group = lane >> 2, tg = lane & 3;
    #pragma unroll
    for (int nt = 0; nt < 4; ++nt) {
        const int n = n0 + wn + nt * 8 + tg * 2;
        const int m = m0 + wm + group;
        #pragma unroll
        for (int e = 0; e < 4; ++e) {
            const int mm = m + (e >> 1) * 8;
            const int nn = n + (e & 1);
            g_part[((size_t)kz * SEQ + mm) * 192 + nn] = acc[nt][e];
        }
    }
}

// ---------------- Pass A2: reduce partials + activations + hi/lo split ----------------
__global__ __launch_bounds__(256) void proj_act(const float* __restrict__ tau)
{
    const int idx = blockIdx.x * 256 + threadIdx.x;   // 0 .. 2048*192-1
    const float inv_tau = 1.0f / tau[0];
    float s = 0.0f;
    #pragma unroll
    for (int p = 0; p < 4; ++p) s += g_part[(size_t)p * (SEQ * 192) + idx];
    const int m = idx / 192;
    const int n = idx - m * 192;
    const float x = s * inv_tau;
    if (n < 160) {
        const float tv = tanhf(x);
        const __nv_bfloat16 th = __float2bfloat16(tv);
        const __nv_bfloat16 tl = __float2bfloat16(tv - __bfloat162float(th));
        if (n < 128) { g_qh[m * 128 + n] = th; g_ql[m * 128 + n] = tl; }
        else { g_kh[m * 32 + (n - 128)] = th; g_kl[m * 32 + (n - 128)] = tl; }
    } else {
        g_v[m * 32 + (n - 160)] = 1.0f / (1.0f + expf(-x));
    }
}

// ---------------- Pass B: suffix attention (MMA G + prefix; no-max softmax) ----------------
__global__ __launch_bounds__(256, 3) void attn_kernel(
    const float* __restrict__ tau,
    const float* __restrict__ ve0,
    const float* __restrict__ ve1)
{
    extern __shared__ float smem[];
    const uint32_t* qh32 = (const uint32_t*)(smem + QHS_OFF);
    const uint32_t* ql32 = (const uint32_t*)(smem + QLS_OFF);
    float* vsb = smem + VS_OFF;
    float* G   = smem + G_OFF;

    const int h  = blockIdx.y;
    const int qb = 31 - blockIdx.x;
    const int q0 = qb * 64;
    const int c  = h >> 2;
    const int t  = threadIdx.x;
    const int w  = t >> 5, lane = t & 31;
    const float inv_tau = 1.0f / tau[0];
    const float scale   = 0.0625f * inv_tau;

    // q halo
    if (t < 192) {
        const int r = t >> 1, half = t & 1;
        const int gq = q0 - 31 + r;
        uint4 v4 = make_uint4(0u, 0u, 0u, 0u);
        const __nv_bfloat16* src = half ? g_ql : g_qh;
        if (gq >= 0 && gq < SEQ) v4 = *(const uint4*)&src[gq * 128 + h * 8];
        float* dst = smem + (half ? QLS_OFF : QHS_OFF);
        *(uint4*)&dst[r * 4] = v4;
    }

    const int a  = t >> 2;
    const int jq = t & 3;
    const int qg = q0 + a;
    const float bias_r = inv_tau / (float)(qg + 1);

    float l_run = 0.0f;
    float acc[8];
    #pragma unroll
    for (int d = 0; d < 8; ++d) acc[d] = 0.0f;

    const int fr = lane >> 2, fq = lane & 3;
    const int fc = fq * 2;

    const int lr = t >> 1, lhalf = t & 1;
    const int lu = t - 192;

    // preload tile 0
    {
        if (t < 192) {
            const int gk = -31 + lr;
            uint4 v4 = make_uint4(0u, 0u, 0u, 0u);
            const __nv_bfloat16* src = lhalf ? g_kl : g_kh;
            if (gk >= 0) v4 = *(const uint4*)&src[gk * 32 + c * 8];
            float* dst = smem + (lhalf ? KLS_OFF : KHS_OFF);
            *(uint4*)&dst[lr * 4] = v4;
        } else {
            #pragma unroll
            for (int rep = 0; rep < 2; ++rep) {
                const int idx = lu * 2 + rep;
                const int r = idx >> 1, half = idx & 1;
                const int gk = r + 1;
                float4 v4 = *(const float4*)&g_v[gk * 32 + c * 8 + half * 4];
                *(float4*)&vsb[r * 8 + half * 4] = v4;
            }
        }
    }

    for (int kb = 0; kb <= qb; ++kb) {
        const int k0 = kb * 64;
        const int buf = kb & 1;
        const uint32_t* kh32 = (const uint32_t*)(smem + KHS_OFF + buf * 384);
        const uint32_t* kl32 = (const uint32_t*)(smem + KLS_OFF + buf * 384);
        const float* vsm = vsb + buf * 512;
        __syncthreads();

        // ---- G via m16n8k8, hi/lo 3x ----
        #pragma unroll
        for (int k9 = 0; k9 < 9; ++k9) {
            const int p  = w + (k9 << 3);
            const int mt = p / 12;
            const int nt = p - mt * 12;
            const int ai = (mt * 16 + fr) * 4 + fq;
            const uint32_t ah0 = qh32[ai],      ah1 = qh32[ai + 32];
            const uint32_t al0 = ql32[ai],      al1 = ql32[ai + 32];
            const int bi = (nt * 8 + fr) * 4 + fq;
            const uint32_t bh = kh32[bi], bl = kl32[bi];
            float cfr[4] = {0.f, 0.f, 0.f, 0.f};
            mma_k8(cfr, ah0, ah1, bh);
            mma_k8(cfr, ah0, ah1, bl);
            mma_k8(cfr, al0, al1, bh);
            float* gp = &G[(mt * 16 + fr) * GSTR + nt * 8 + fc];
            gp[0] = cfr[0]; gp[1] = cfr[1];
            gp[8 * GSTR] = cfr[2]; gp[8 * GSTR + 1] = cfr[3];
        }
        __syncthreads();

        // ---- diagonal prefix; v-prefetch on spare threads ----
        if (t < 191) {
            const int dlt = t - 95;
            const int ad  = dlt < 0 ? -dlt : dlt;
            const int L   = 96 - ad;
            int off = (dlt > 0) ? dlt * GSTR : -dlt;
            float carry = 0.0f;
            int s = 0;
            for (; s + 4 <= L; s += 4) {
                const float e0 = G[off];
                const float e1 = G[off + (GSTR + 1)];
                const float e2 = G[off + 2 * (GSTR + 1)];
                const float e3 = G[off + 3 * (GSTR + 1)];
                const float c0 = carry + e0;
                const float c1 = c0 + e1;
                const float c2 = c1 + e2;
                const float c3 = c2 + e3;
                G[off] = c0;
                G[off + (GSTR + 1)]     = c1;
                G[off + 2 * (GSTR + 1)] = c2;
                G[off + 3 * (GSTR + 1)] = c3;
                carry = c3;
                off += 4 * (GSTR + 1);
            }
            for (; s < L; ++s) { carry += G[off]; G[off] = carry; off += GSTR + 1; }
        } else if (t >= 192 && kb < qb) {
            const int nk0 = k0 + 64;
            #pragma unroll
            for (int rep = 0; rep < 2; ++rep) {
                const int idx = lu * 2 + rep;
                const int r = idx >> 1, half = idx & 1;
                const int gk = nk0 + r + 1;
                float4 v4 = make_float4(0.f, 0.f, 0.f, 0.f);
                if (gk < SEQ) v4 = *(const float4*)&g_v[gk * 32 + c * 8 + half * 4];
                *(float4*)&vsb[(buf ^ 1) * 512 + r * 8 + half * 4] = v4;
            }
        }
        __syncthreads();

        // ---- k-halo prefetch for next tile ----
        if (kb < qb && t < 192) {
            const int gk = k0 + 64 - 31 + lr;
            const __nv_bfloat16* src = lhalf ? g_kl : g_kh;
            const uint4 v4 = *(const uint4*)&src[gk * 32 + c * 8];
            float* dst = smem + (lhalf ? KLS_OFF : KHS_OFF) + (buf ^ 1) * 384;
            *(uint4*)&dst[lr * 4] = v4;
        }

        // ---- scores + no-max softmax accumulation ----
        const int browH = (a + 31) * GSTR + 31;
        const int browL = (a - 1) * GSTR - 1;
        #pragma unroll
        for (int bb = 0; bb < 16; ++bb) {
            const int b  = (bb << 2) | jq;
            const int kg = k0 + b;
            if (kg < qg) {
                const float hi = G[browH + b];
                const float lo = (a > 0 && b > 0) ? G[browL + b] : 0.0f;
                const float s = (hi - lo) * scale + (float)kg * bias_r;
                const float e = __expf(s);
                l_run += e;
                const float4 v0 = *(const float4*)&vsm[b * 8];
                const float4 v1 = *(const float4*)&vsm[b * 8 + 4];
                acc[0] = fmaf(e, v0.x, acc[0]); acc[1] = fmaf(e, v0.y, acc[1]);
                acc[2] = fmaf(e, v0.z, acc[2]); acc[3] = fmaf(e, v0.w, acc[3]);
                acc[4] = fmaf(e, v1.x, acc[4]); acc[5] = fmaf(e, v1.y, acc[5]);
                acc[6] = fmaf(e, v1.z, acc[6]); acc[7] = fmaf(e, v1.w, acc[7]);
            }
        }
    }

    // sum-merge the 4 threads of each query row
    #pragma unroll
    for (int off = 1; off < 4; off <<= 1) {
        l_run += __shfl_xor_sync(0xffffffffu, l_run, off);
        #pragma unroll
        for (int d = 0; d < 8; ++d)
            acc[d] += __shfl_xor_sync(0xffffffffu, acc[d], off);
    }
    if (jq == 0) {
        const float invl = (l_run > 0.0f) ? 1.0f / l_run : 0.0f;
        #pragma unroll
        for (int d = 0; d < 8; ++d) {
            const int f = h * 8 + d;
            const float e0 = ve0[f], e1 = ve1[f];
            const float o  = acc[d] * invl;
            const float fin = o * (e1 - e0) + e0;
            const __nv_bfloat16 fh = __float2bfloat16(fin);
            const __nv_bfloat16 fl = __float2bfloat16(fin - __bfloat162float(fh));
            g_oh[qg * 128 + f] = fh;
            g_ol[qg * 128 + f] = fl;
        }
    }
}

// ---------------- Pass C: output projection via MMA (K=128) ----------------
__global__ __launch_bounds__(256) void out_mma(float* __restrict__ out)
{
    __shared__ __nv_bfloat16 sAh[2][64 * PSTR], sAl[2][64 * PSTR];
    __shared__ __nv_bfloat16 sBh[2][64 * PSTR], sBl[2][64 * PSTR];

    const int m0 = blockIdx.x * 64;
    const int n0 = blockIdx.y * 64;
    const int t  = threadIdx.x;
    const int w  = t >> 5, lane = t & 31;
    const int wm = (w & 3) * 16;
    const int wn = (w >> 2) * 32;

    const int lrow = t >> 2;
    const int lcol = (t & 3) * 8;
    const size_t aoff0 = (size_t)(m0 + lrow) * 128 + lcol;
    const size_t boff0 = (size_t)(n0 + lrow) * 128 + lcol;
    const int sidx = lrow * PSTR + lcol;

    const int seg = lane >> 3, lr8 = lane & 7;
    const int a_r = wm + (seg & 1) * 8 + lr8;
    const int a_c0 = (seg >> 1) * 8;

    float acc[4][4] = {};

    uint4 pah = *(const uint4*)&g_oh[aoff0];
    uint4 pal = *(const uint4*)&g_ol[aoff0];
    uint4 pbh = *(const uint4*)&g_woh[boff0];
    uint4 pbl = *(const uint4*)&g_wol[boff0];

    for (int stage = 0; stage < 4; ++stage) {
        const int buf = stage & 1;
        __syncthreads();
        *(uint4*)&sAh[buf][sidx] = pah;
        *(uint4*)&sAl[buf][sidx] = pal;
        *(uint4*)&sBh[buf][sidx] = pbh;
        *(uint4*)&sBl[buf][sidx] = pbl;
        __syncthreads();
        if (stage + 1 < 4) {
            const size_t koff = (size_t)(stage + 1) * 32;
            pah = *(const uint4*)&g_oh[aoff0 + koff];
            pal = *(const uint4*)&g_ol[aoff0 + koff];
            pbh = *(const uint4*)&g_woh[boff0 + koff];
            pbl = *(const uint4*)&g_wol[boff0 + koff];
        }
        #pragma unroll
        for (int ks = 0; ks < 32; ks += 16) {
            uint32_t ah[4], al[4];
            {
                const int ac = ks + a_c0;
                ldsm_x4(ah, smem_u32(&sAh[buf][a_r * PSTR + ac]));
                ldsm_x4(al, smem_u32(&sAl[buf][a_r * PSTR + ac]));
            }
            #pragma unroll
            for (int nb = 0; nb < 32; nb += 16) {
                const int b_r = wn + nb + (seg >> 1) * 8 + lr8;
                const int b_c = ks + (seg & 1) * 8;
                uint32_t bh[4], bl[4];
                ldsm_x4(bh, smem_u32(&sBh[buf][b_r * PSTR + b_c]));
                ldsm_x4(bl, smem_u32(&sBl[buf][b_r * PSTR + b_c]));
                const int nt = nb >> 3;
                mma_bf16(acc[nt],     ah, bh[0], bh[1]);
                mma_bf16(acc[nt],     ah, bl[0], bl[1]);
                mma_bf16(acc[nt],     al, bh[0], bh[1]);
                mma_bf16(acc[nt + 1], ah, bh[2], bh[3]);
                mma_bf16(acc[nt + 1], ah, bl[2], bl[3]);
                mma_bf16(acc[nt + 1], al, bh[2], bh[3]);
            }
        }
    }

    const int group = lane >> 2, tg = lane & 3;
    #pragma unroll
    for (int nt = 0; nt < 4; ++nt) {
        const int n = n0 + wn + nt * 8 + tg * 2;
        const int m = m0 + wm + group;
        #pragma unroll
        for (int e = 0; e < 4; ++e) {
            const int mm = m + (e >> 1) * 8;
            const int nn = n + (e & 1);
            out[(size_t)mm * DMODEL + nn] = acc[nt][e];
        }
    }
}

// ---------------- launch ----------------
extern "C" void kernel_launch(void* const* d_in, const int* in_sizes, int n_in,
                              void* d_out, int out_size)
{
    const float* X   = (const float*)d_in[0];
    const float* Wq  = (const float*)d_in[1];
    const float* Wk  = (const float*)d_in[2];
    const float* Wv  = (const float*)d_in[3];
    const float* Wo  = (const float*)d_in[4];
    const float* ve0 = (const float*)d_in[5];
    const float* ve1 = (const float*)d_in[6];
    const float* tau = (const float*)d_in[7];
    float* out = (float*)d_out;
    (void)in_sizes; (void)n_in; (void)out_size;

    cudaFuncSetAttribute(attn_kernel,
                         cudaFuncAttributeMaxDynamicSharedMemorySize,
                         SMEM_FLOATS * (int)sizeof(float));

    convert_x <<<4096, 256>>>(X);
    convert_w <<<384, 256>>>(Wq, Wk, Wv);
    convert_wo<<<256, 256>>>(Wo);
    proj_mma  <<<dim3(32, 3, 4), 256>>>();
    proj_act  <<<1536, 256>>>(tau);
    attn_kernel<<<dim3(32, 16), 256, SMEM_FLOATS * sizeof(float)>>>(tau, ve0, ve1);
    out_mma   <<<dim3(32, 32), 256>>>(out);
}

// round 16
// speedup vs baseline: 1.4808x; 1.1944x over previous
#include <cuda_runtime.h>
#include <cuda_bf16.h>
#include <cstdint>
#include <math.h>

#define SEQ    2048
#define DMODEL 2048
#define NEGINF (-1e30f)

// ---------------- scratch ----------------
__device__ __nv_bfloat16 g_oh[SEQ * 128];      // affined attn out hi
__device__ __nv_bfloat16 g_ol[SEQ * 128];      // affined attn out lo
__device__ __nv_bfloat16 g_qh[SEQ * 128];      // tanh(q) hi
__device__ __nv_bfloat16 g_ql[SEQ * 128];      // tanh(q) lo
__device__ __nv_bfloat16 g_kh[SEQ * 32];       // tanh(k) hi
__device__ __nv_bfloat16 g_kl[SEQ * 32];       // tanh(k) lo
__device__ float g_v[SEQ * 32];                // sigmoid(v) fp32
__device__ __nv_bfloat16 g_xh[SEQ * DMODEL];   // X hi
__device__ __nv_bfloat16 g_xl[SEQ * DMODEL];   // X lo
__device__ __nv_bfloat16 g_wh[192 * DMODEL];   // [Wq;Wk;Wv] hi
__device__ __nv_bfloat16 g_wl[192 * DMODEL];   // [Wq;Wk;Wv] lo
__device__ __nv_bfloat16 g_woh[DMODEL * 128];  // Wo hi
__device__ __nv_bfloat16 g_wol[DMODEL * 128];  // Wo lo
__device__ float g_part[4 * SEQ * 192];        // proj split-K partials
__device__ float g_pl[8 * SEQ * 16];           // attn split-K: partial l
__device__ float g_pacc[8 * SEQ * 128];        // attn split-K: partial acc

// attn smem layout (float units). G row stride 101: prefix lane stride
// 101 == 5 (mod 32) -> conflict-free.
#define GSTR     101
#define QHS_OFF  0
#define QLS_OFF  384
#define KHS_OFF  768
#define KLS_OFF  1536
#define VS_OFF   2304
#define G_OFF    3328
#define SMEM_FLOATS (G_OFF + 96 * GSTR)    // 13024 floats = 52096 B

// ---------------- mma helpers ----------------
__device__ __forceinline__ uint32_t smem_u32(const void* p) {
    return (uint32_t)__cvta_generic_to_shared(p);
}
__device__ __forceinline__ void ldsm_x4(uint32_t r[4], uint32_t addr) {
    asm volatile("ldmatrix.sync.aligned.m8n8.x4.shared.b16 {%0,%1,%2,%3}, [%4];"
        : "=r"(r[0]), "=r"(r[1]), "=r"(r[2]), "=r"(r[3]) : "r"(addr));
}
__device__ __forceinline__ void mma_bf16(float c[4], const uint32_t a[4],
                                         uint32_t b0, uint32_t b1) {
    asm volatile("mma.sync.aligned.m16n8k16.row.col.f32.bf16.bf16.f32 "
        "{%0,%1,%2,%3},{%4,%5,%6,%7},{%8,%9},{%0,%1,%2,%3};"
        : "+f"(c[0]), "+f"(c[1]), "+f"(c[2]), "+f"(c[3])
        : "r"(a[0]), "r"(a[1]), "r"(a[2]), "r"(a[3]), "r"(b0), "r"(b1));
}
__device__ __forceinline__ void mma_k8(float c[4], uint32_t a0, uint32_t a1,
                                       uint32_t b) {
    asm volatile("mma.sync.aligned.m16n8k8.row.col.f32.bf16.bf16.f32 "
        "{%0,%1,%2,%3},{%4,%5},{%6},{%0,%1,%2,%3};"
        : "+f"(c[0]), "+f"(c[1]), "+f"(c[2]), "+f"(c[3])
        : "r"(a0), "r"(a1), "r"(b));
}

// ---------------- converts: fp32 -> bf16 hi/lo ----------------
__global__ __launch_bounds__(256) void convert_x(const float* __restrict__ X)
{
    const int i4 = (blockIdx.x * 256 + threadIdx.x) * 4;
    const float4 v = *(const float4*)(X + i4);
    const float xs[4] = {v.x, v.y, v.z, v.w};
    __nv_bfloat16 hs[4], ls[4];
    #pragma unroll
    for (int i = 0; i < 4; ++i) {
        hs[i] = __float2bfloat16(xs[i]);
        ls[i] = __float2bfloat16(xs[i] - __bfloat162float(hs[i]));
    }
    *(uint2*)&g_xh[i4] = *(uint2*)hs;
    *(uint2*)&g_xl[i4] = *(uint2*)ls;
}

__global__ __launch_bounds__(256) void convert_w(
    const float* __restrict__ Wq,
    const float* __restrict__ Wk,
    const float* __restrict__ Wv)
{
    const int i4 = (blockIdx.x * 256 + threadIdx.x) * 4;
    const int n = i4 >> 11, col = i4 & 2047;
    const float* src;
    if (n < 128)      src = Wq + (size_t)n * DMODEL;
    else if (n < 160) src = Wk + (size_t)(n - 128) * DMODEL;
    else              src = Wv + (size_t)(n - 160) * DMODEL;
    const float4 v = *(const float4*)(src + col);
    const float xs[4] = {v.x, v.y, v.z, v.w};
    __nv_bfloat16 hs[4], ls[4];
    #pragma unroll
    for (int i = 0; i < 4; ++i) {
        hs[i] = __float2bfloat16(xs[i]);
        ls[i] = __float2bfloat16(xs[i] - __bfloat162float(hs[i]));
    }
    *(uint2*)&g_wh[i4] = *(uint2*)hs;
    *(uint2*)&g_wl[i4] = *(uint2*)ls;
}

__global__ __launch_bounds__(256) void convert_wo(const float* __restrict__ Wo)
{
    const int i4 = (blockIdx.x * 256 + threadIdx.x) * 4;
    const float4 v = *(const float4*)(Wo + i4);
    const float xs[4] = {v.x, v.y, v.z, v.w};
    __nv_bfloat16 hs[4], ls[4];
    #pragma unroll
    for (int i = 0; i < 4; ++i) {
        hs[i] = __float2bfloat16(xs[i]);
        ls[i] = __float2bfloat16(xs[i] - __bfloat162float(hs[i]));
    }
    *(uint2*)&g_woh[i4] = *(uint2*)hs;
    *(uint2*)&g_wol[i4] = *(uint2*)ls;
}

// ---------------- Pass A1: split-K tensor-core QKV projection ----------------
#define PSTR 40
__global__ __launch_bounds__(256) void proj_mma()
{
    __shared__ __nv_bfloat16 sAh[2][64 * PSTR], sAl[2][64 * PSTR];
    __shared__ __nv_bfloat16 sBh[2][64 * PSTR], sBl[2][64 * PSTR];

    const int m0 = blockIdx.x * 64;
    const int n0 = blockIdx.y * 64;
    const int kz = blockIdx.z;
    const size_t kbase = (size_t)kz * 512;
    const int t  = threadIdx.x;
    const int w  = t >> 5, lane = t & 31;
    const int wm = (w & 3) * 16;
    const int wn = (w >> 2) * 32;

    const int lrow = t >> 2;
    const int lcol = (t & 3) * 8;
    const size_t aoff0 = (size_t)(m0 + lrow) * DMODEL + kbase + lcol;
    const size_t boff0 = (size_t)(n0 + lrow) * DMODEL + kbase + lcol;
    const int sidx = lrow * PSTR + lcol;

    const int seg = lane >> 3, lr8 = lane & 7;
    const int a_r = wm + (seg & 1) * 8 + lr8;
    const int a_c0 = (seg >> 1) * 8;

    float acc[4][4] = {};

    uint4 pah = *(const uint4*)&g_xh[aoff0];
    uint4 pal = *(const uint4*)&g_xl[aoff0];
    uint4 pbh = *(const uint4*)&g_wh[boff0];
    uint4 pbl = *(const uint4*)&g_wl[boff0];

    for (int stage = 0; stage < 16; ++stage) {
        const int buf = stage & 1;
        __syncthreads();
        *(uint4*)&sAh[buf][sidx] = pah;
        *(uint4*)&sAl[buf][sidx] = pal;
        *(uint4*)&sBh[buf][sidx] = pbh;
        *(uint4*)&sBl[buf][sidx] = pbl;
        __syncthreads();
        if (stage + 1 < 16) {
            const size_t koff = (size_t)(stage + 1) * 32;
            pah = *(const uint4*)&g_xh[aoff0 + koff];
            pal = *(const uint4*)&g_xl[aoff0 + koff];
            pbh = *(const uint4*)&g_wh[boff0 + koff];
            pbl = *(const uint4*)&g_wl[boff0 + koff];
        }
        #pragma unroll
        for (int ks = 0; ks < 32; ks += 16) {
            uint32_t ah[4], al[4];
            {
                const int ac = ks + a_c0;
                ldsm_x4(ah, smem_u32(&sAh[buf][a_r * PSTR + ac]));
                ldsm_x4(al, smem_u32(&sAl[buf][a_r * PSTR + ac]));
            }
            #pragma unroll
            for (int nb = 0; nb < 32; nb += 16) {
                const int b_r = wn + nb + (seg >> 1) * 8 + lr8;
                const int b_c = ks + (seg & 1) * 8;
                uint32_t bh[4], bl[4];
                ldsm_x4(bh, smem_u32(&sBh[buf][b_r * PSTR + b_c]));
                ldsm_x4(bl, smem_u32(&sBl[buf][b_r * PSTR + b_c]));
                const int nt = nb >> 3;
                mma_bf16(acc[nt],     ah, bh[0], bh[1]);
                mma_bf16(acc[nt],     ah, bl[0], bl[1]);
                mma_bf16(acc[nt],     al, bh[0], bh[1]);
                mma_bf16(acc[nt + 1], ah, bh[2], bh[3]);
                mma_bf16(acc[nt + 1], ah, bl[2], bl[3]);
                mma_bf16(acc[nt + 1], al, bh[2], bh[3]);
            }
        }
    }

    const int group = lane >> 2, tg = lane & 3;
    #pragma unroll
    for (int nt = 0; nt < 4; ++nt) {
        const int n = n0 + wn + nt * 8 + tg * 2;
        const int m = m0 + wm + group;
        #pragma unroll
        for (int e = 0; e < 4; ++e) {
            const int mm = m + (e >> 1) * 8;
            const int nn = n + (e & 1);
            g_part[((size_t)kz * SEQ + mm) * 192 + nn] = acc[nt][e];
        }
    }
}

// ---------------- Pass A2: reduce partials + activations + hi/lo split ----------------
__global__ __launch_bounds__(256) void proj_act(const float* __restrict__ tau)
{
    const int idx = blockIdx.x * 256 + threadIdx.x;
    const float inv_tau = 1.0f / tau[0];
    float s = 0.0f;
    #pragma unroll
    for (int p = 0; p < 4; ++p) s += g_part[(size_t)p * (SEQ * 192) + idx];
    const int m = idx / 192;
    const int n = idx - m * 192;
    const float x = s * inv_tau;
    if (n < 160) {
        const float tv = tanhf(x);
        const __nv_bfloat16 th = __float2bfloat16(tv);
        const __nv_bfloat16 tl = __float2bfloat16(tv - __bfloat162float(th));
        if (n < 128) { g_qh[m * 128 + n] = th; g_ql[m * 128 + n] = tl; }
        else { g_kh[m * 32 + (n - 128)] = th; g_kl[m * 32 + (n - 128)] = tl; }
    } else {
        g_v[m * 32 + (n - 160)] = 1.0f / (1.0f + expf(-x));
    }
}

// ---------------- Pass B: split-K suffix attention ----------------
// grid (8, 32, 16): kz key-chunk (4 tiles), qb, head. Partials additive
// (no-max softmax) -> g_pl / g_pacc; attn_fin merges.
__global__ __launch_bounds__(256, 3) void attn_kernel(const float* __restrict__ tau)
{
    extern __shared__ float smem[];
    const uint32_t* qh32 = (const uint32_t*)(smem + QHS_OFF);
    const uint32_t* ql32 = (const uint32_t*)(smem + QLS_OFF);
    float* vsb = smem + VS_OFF;
    float* G   = smem + G_OFF;

    const int kz = blockIdx.x;
    const int qb = blockIdx.y;
    const int h  = blockIdx.z;
    const int q0 = qb * 64;
    const int c  = h >> 2;
    const int t  = threadIdx.x;
    const int kb0 = kz * 4;

    // inactive chunk: zero partial slice and exit
    if (kb0 > qb) {
        if (t < 64) {
            const int qg = q0 + t;
            g_pl[((size_t)kz * SEQ + qg) * 16 + h] = 0.0f;
            float* pa = &g_pacc[((size_t)kz * SEQ + qg) * 128 + h * 8];
            #pragma unroll
            for (int d = 0; d < 8; ++d) pa[d] = 0.0f;
        }
        return;
    }
    const int kb1 = (kb0 + 3 < qb) ? kb0 + 3 : qb;

    const int w  = t >> 5, lane = t & 31;
    const float inv_tau = 1.0f / tau[0];
    const float scale   = 0.0625f * inv_tau;

    // q halo
    if (t < 192) {
        const int r = t >> 1, half = t & 1;
        const int gq = q0 - 31 + r;
        uint4 v4 = make_uint4(0u, 0u, 0u, 0u);
        const __nv_bfloat16* src = half ? g_ql : g_qh;
        if (gq >= 0 && gq < SEQ) v4 = *(const uint4*)&src[gq * 128 + h * 8];
        float* dst = smem + (half ? QLS_OFF : QHS_OFF);
        *(uint4*)&dst[r * 4] = v4;
    }

    const int a  = t >> 2;
    const int jq = t & 3;
    const int qg = q0 + a;
    const float bias_r = inv_tau / (float)(qg + 1);

    float l_run = 0.0f;
    float acc[8];
    #pragma unroll
    for (int d = 0; d < 8; ++d) acc[d] = 0.0f;

    const int fr = lane >> 2, fq = lane & 3;
    const int fc = fq * 2;

    const int lr = t >> 1, lhalf = t & 1;
    const int lu = t - 192;

    // preload first tile of chunk
    {
        const int k0 = kb0 * 64;
        if (t < 192) {
            const int gk = k0 - 31 + lr;
            uint4 v4 = make_uint4(0u, 0u, 0u, 0u);
            const __nv_bfloat16* src = lhalf ? g_kl : g_kh;
            if (gk >= 0 && gk < SEQ) v4 = *(const uint4*)&src[gk * 32 + c * 8];
            float* dst = smem + (lhalf ? KLS_OFF : KHS_OFF);
            *(uint4*)&dst[lr * 4] = v4;
        } else {
            #pragma unroll
            for (int rep = 0; rep < 2; ++rep) {
                const int idx = lu * 2 + rep;
                const int r = idx >> 1, half = idx & 1;
                const int gk = k0 + r + 1;
                float4 v4 = make_float4(0.f, 0.f, 0.f, 0.f);
                if (gk < SEQ) v4 = *(const float4*)&g_v[gk * 32 + c * 8 + half * 4];
                *(float4*)&vsb[r * 8 + half * 4] = v4;
            }
        }
    }

    for (int kb = kb0; kb <= kb1; ++kb) {
        const int k0 = kb * 64;
        const int buf = (kb - kb0) & 1;
        const uint32_t* kh32 = (const uint32_t*)(smem + KHS_OFF + buf * 384);
        const uint32_t* kl32 = (const uint32_t*)(smem + KLS_OFF + buf * 384);
        const float* vsm = vsb + buf * 512;
        __syncthreads();

        // ---- G via m16n8k8, hi/lo 3x ----
        #pragma unroll
        for (int k9 = 0; k9 < 9; ++k9) {
            const int p  = w + (k9 << 3);
            const int mt = p / 12;
            const int nt = p - mt * 12;
            const int ai = (mt * 16 + fr) * 4 + fq;
            const uint32_t ah0 = qh32[ai],      ah1 = qh32[ai + 32];
            const uint32_t al0 = ql32[ai],      al1 = ql32[ai + 32];
            const int bi = (nt * 8 + fr) * 4 + fq;
            const uint32_t bh = kh32[bi], bl = kl32[bi];
            float cfr[4] = {0.f, 0.f, 0.f, 0.f};
            mma_k8(cfr, ah0, ah1, bh);
            mma_k8(cfr, ah0, ah1, bl);
            mma_k8(cfr, al0, al1, bh);
            float* gp = &G[(mt * 16 + fr) * GSTR + nt * 8 + fc];
            gp[0] = cfr[0]; gp[1] = cfr[1];
            gp[8 * GSTR] = cfr[2]; gp[8 * GSTR + 1] = cfr[3];
        }
        __syncthreads();

        // ---- diagonal prefix; v-prefetch on spare threads ----
        if (t < 191) {
            const int dlt = t - 95;
            const int ad  = dlt < 0 ? -dlt : dlt;
            const int L   = 96 - ad;
            int off = (dlt > 0) ? dlt * GSTR : -dlt;
            float carry = 0.0f;
            int s = 0;
            for (; s + 4 <= L; s += 4) {
                const float e0 = G[off];
                const float e1 = G[off + (GSTR + 1)];
                const float e2 = G[off + 2 * (GSTR + 1)];
                const float e3 = G[off + 3 * (GSTR + 1)];
                const float c0 = carry + e0;
                const float c1 = c0 + e1;
                const float c2 = c1 + e2;
                const float c3 = c2 + e3;
                G[off] = c0;
                G[off + (GSTR + 1)]     = c1;
                G[off + 2 * (GSTR + 1)] = c2;
                G[off + 3 * (GSTR + 1)] = c3;
                carry = c3;
                off += 4 * (GSTR + 1);
            }
            for (; s < L; ++s) { carry += G[off]; G[off] = carry; off += GSTR + 1; }
        } else if (t >= 192 && kb < kb1) {
            const int nk0 = k0 + 64;
            #pragma unroll
            for (int rep = 0; rep < 2; ++rep) {
                const int idx = lu * 2 + rep;
                const int r = idx >> 1, half = idx & 1;
                const int gk = nk0 + r + 1;
                float4 v4 = make_float4(0.f, 0.f, 0.f, 0.f);
                if (gk < SEQ) v4 = *(const float4*)&g_v[gk * 32 + c * 8 + half * 4];
                *(float4*)&vsb[(buf ^ 1) * 512 + r * 8 + half * 4] = v4;
            }
        }
        __syncthreads();

        // ---- k-halo prefetch for next tile ----
        if (kb < kb1 && t < 192) {
            const int gk = k0 + 64 - 31 + lr;
            const __nv_bfloat16* src = lhalf ? g_kl : g_kh;
            const uint4 v4 = *(const uint4*)&src[gk * 32 + c * 8];
            float* dst = smem + (lhalf ? KLS_OFF : KHS_OFF) + (buf ^ 1) * 384;
            *(uint4*)&dst[lr * 4] = v4;
        }

        // ---- scores + no-max softmax accumulation ----
        const int browH = (a + 31) * GSTR + 31;
        const int browL = (a - 1) * GSTR - 1;
        #pragma unroll
        for (int bb = 0; bb < 16; ++bb) {
            const int b  = (bb << 2) | jq;
            const int kg = k0 + b;
            if (kg < qg) {
                const float hi = G[browH + b];
                const float lo = (a > 0 && b > 0) ? G[browL + b] : 0.0f;
                const float s = (hi - lo) * scale + (float)kg * bias_r;
                const float e = __expf(s);
                l_run += e;
                const float4 v0 = *(const float4*)&vsm[b * 8];
                const float4 v1 = *(const float4*)&vsm[b * 8 + 4];
                acc[0] = fmaf(e, v0.x, acc[0]); acc[1] = fmaf(e, v0.y, acc[1]);
                acc[2] = fmaf(e, v0.z, acc[2]); acc[3] = fmaf(e, v0.w, acc[3]);
                acc[4] = fmaf(e, v1.x, acc[4]); acc[5] = fmaf(e, v1.y, acc[5]);
                acc[6] = fmaf(e, v1.z, acc[6]); acc[7] = fmaf(e, v1.w, acc[7]);
            }
        }
    }

    // sum-merge the 4 threads of each query row, write partials
    #pragma unroll
    for (int off = 1; off < 4; off <<= 1) {
        l_run += __shfl_xor_sync(0xffffffffu, l_run, off);
        #pragma unroll
        for (int d = 0; d < 8; ++d)
            acc[d] += __shfl_xor_sync(0xffffffffu, acc[d], off);
    }
    if (jq == 0) {
        g_pl[((size_t)kz * SEQ + qg) * 16 + h] = l_run;
        float* pa = &g_pacc[((size_t)kz * SEQ + qg) * 128 + h * 8];
        #pragma unroll
        for (int d = 0; d < 8; ++d) pa[d] = acc[d];
    }
}

// ---------------- Pass B2: merge attn partials, affine, bf16 split ----------------
__global__ __launch_bounds__(256) void attn_fin(
    const float* __restrict__ ve0,
    const float* __restrict__ ve1)
{
    const int idx = blockIdx.x * 256 + threadIdx.x;   // 0 .. 2048*128-1
    const int q = idx >> 7;
    const int f = idx & 127;
    const int h = f >> 3;
    float l = 0.0f, s = 0.0f;
    #pragma unroll
    for (int kz = 0; kz < 8; ++kz) {
        l += g_pl[((size_t)kz * SEQ + q) * 16 + h];
        s += g_pacc[((size_t)kz * SEQ + q) * 128 + f];
    }
    const float invl = (l > 0.0f) ? 1.0f / l : 0.0f;
    const float o = s * invl;
    const float fin = o * (ve1[f] - ve0[f]) + ve0[f];
    const __nv_bfloat16 fh = __float2bfloat16(fin);
    const __nv_bfloat16 fl = __float2bfloat16(fin - __bfloat162float(fh));
    g_oh[idx] = fh;
    g_ol[idx] = fl;
}

// ---------------- Pass C: output projection via MMA (K=128) ----------------
__global__ __launch_bounds__(256) void out_mma(float* __restrict__ out)
{
    __shared__ __nv_bfloat16 sAh[2][64 * PSTR], sAl[2][64 * PSTR];
    __shared__ __nv_bfloat16 sBh[2][64 * PSTR], sBl[2][64 * PSTR];

    const int m0 = blockIdx.x * 64;
    const int n0 = blockIdx.y * 64;
    const int t  = threadIdx.x;
    const int w  = t >> 5, lane = t & 31;
    const int wm = (w & 3) * 16;
    const int wn = (w >> 2) * 32;

    const int lrow = t >> 2;
    const int lcol = (t & 3) * 8;
    const size_t aoff0 = (size_t)(m0 + lrow) * 128 + lcol;
    const size_t boff0 = (size_t)(n0 + lrow) * 128 + lcol;
    const int sidx = lrow * PSTR + lcol;

    const int seg = lane >> 3, lr8 = lane & 7;
    const int a_r = wm + (seg & 1) * 8 + lr8;
    const int a_c0 = (seg >> 1) * 8;

    float acc[4][4] = {};

    uint4 pah = *(const uint4*)&g_oh[aoff0];
    uint4 pal = *(const uint4*)&g_ol[aoff0];
    uint4 pbh = *(const uint4*)&g_woh[boff0];
    uint4 pbl = *(const uint4*)&g_wol[boff0];

    for (int stage = 0; stage < 4; ++stage) {
        const int buf = stage & 1;
        __syncthreads();
        *(uint4*)&sAh[buf][sidx] = pah;
        *(uint4*)&sAl[buf][sidx] = pal;
        *(uint4*)&sBh[buf][sidx] = pbh;
        *(uint4*)&sBl[buf][sidx] = pbl;
        __syncthreads();
        if (stage + 1 < 4) {
            const size_t koff = (size_t)(stage + 1) * 32;
            pah = *(const uint4*)&g_oh[aoff0 + koff];
            pal = *(const uint4*)&g_ol[aoff0 + koff];
            pbh = *(const uint4*)&g_woh[boff0 + koff];
            pbl = *(const uint4*)&g_wol[boff0 + koff];
        }
        #pragma unroll
        for (int ks = 0; ks < 32; ks += 16) {
            uint32_t ah[4], al[4];
            {
                const int ac = ks + a_c0;
                ldsm_x4(ah, smem_u32(&sAh[buf][a_r * PSTR + ac]));
                ldsm_x4(al, smem_u32(&sAl[buf][a_r * PSTR + ac]));
            }
            #pragma unroll
            for (int nb = 0; nb < 32; nb += 16) {
                const int b_r = wn + nb + (seg >> 1) * 8 + lr8;
                const int b_c = ks + (seg & 1) * 8;
                uint32_t bh[4], bl[4];
                ldsm_x4(bh, smem_u32(&sBh[buf][b_r * PSTR + b_c]));
                ldsm_x4(bl, smem_u32(&sBl[buf][b_r * PSTR + b_c]));
                const int nt = nb >> 3;
                mma_bf16(acc[nt],     ah, bh[0], bh[1]);
                mma_bf16(acc[nt],     ah, bl[0], bl[1]);
                mma_bf16(acc[nt],     al, bh[0], bh[1]);
                mma_bf16(acc[nt + 1], ah, bh[2], bh[3]);
                mma_bf16(acc[nt + 1], ah, bl[2], bl[3]);
                mma_bf16(acc[nt + 1], al, bh[2], bh[3]);
            }
        }
    }

    const int group = lane >> 2, tg = lane & 3;
    #pragma unroll
    for (int nt = 0; nt < 4; ++nt) {
        const int n = n0 + wn + nt * 8 + tg * 2;
        const int m = m0 + wm + group;
        #pragma unroll
        for (int e = 0; e < 4; ++e) {
            const int mm = m + (e >> 1) * 8;
            const int nn = n + (e & 1);
            out[(size_t)mm * DMODEL + nn] = acc[nt][e];
        }
    }
}

// ---------------- launch ----------------
extern "C" void kernel_launch(void* const* d_in, const int* in_sizes, int n_in,
                              void* d_out, int out_size)
{
    const float* X   = (const float*)d_in[0];
    const float* Wq  = (const float*)d_in[1];
    const float* Wk  = (const float*)d_in[2];
    const float* Wv  = (const float*)d_in[3];
    const float* Wo  = (const float*)d_in[4];
    const float* ve0 = (const float*)d_in[5];
    const float* ve1 = (const float*)d_in[6];
    const float* tau = (const float*)d_in[7];
    float* out = (float*)d_out;
    (void)in_sizes; (void)n_in; (void)out_size;

    cudaFuncSetAttribute(attn_kernel,
                         cudaFuncAttributeMaxDynamicSharedMemorySize,
                         SMEM_FLOATS * (int)sizeof(float));

    convert_x <<<4096, 256>>>(X);
    convert_w <<<384, 256>>>(Wq, Wk, Wv);
    convert_wo<<<256, 256>>>(Wo);
    proj_mma  <<<dim3(32, 3, 4), 256>>>();
    proj_act  <<<1536, 256>>>(tau);
    attn_kernel<<<dim3(8, 32, 16), 256, SMEM_FLOATS * sizeof(float)>>>(tau);
    attn_fin  <<<1024, 256>>>(ve0, ve1);
    out_mma   <<<dim3(32, 32), 256>>>(out);
}

// round 17
// speedup vs baseline: 1.5240x; 1.0292x over previous
#include <cuda_runtime.h>
#include <cuda_bf16.h>
#include <cstdint>
#include <math.h>

#define SEQ    2048
#define DMODEL 2048
#define NEGINF (-1e30f)

// ---------------- scratch ----------------
__device__ __nv_bfloat16 g_oh[SEQ * 128];      // affined attn out hi
__device__ __nv_bfloat16 g_ol[SEQ * 128];      // affined attn out lo
__device__ __nv_bfloat16 g_qh[SEQ * 128];      // tanh(q) hi
__device__ __nv_bfloat16 g_ql[SEQ * 128];      // tanh(q) lo
__device__ __nv_bfloat16 g_kh[SEQ * 32];       // tanh(k) hi
__device__ __nv_bfloat16 g_kl[SEQ * 32];       // tanh(k) lo
__device__ float g_v[SEQ * 32];                // sigmoid(v) fp32
__device__ float g_part[8 * SEQ * 192];        // proj split-K partials
__device__ float g_pl[8 * SEQ * 16];           // attn split-K: partial l
__device__ float g_pacc[8 * SEQ * 128];        // attn split-K: partial acc

// attn smem layout (float units). G row stride 101: prefix lane stride
// 101 == 5 (mod 32) -> conflict-free.
#define GSTR     101
#define QHS_OFF  0
#define QLS_OFF  384
#define KHS_OFF  768
#define KLS_OFF  1536
#define VS_OFF   2304
#define G_OFF    3328
#define SMEM_FLOATS (G_OFF + 96 * GSTR)    // 13024 floats = 52096 B

// ---------------- mma helpers ----------------
__device__ __forceinline__ uint32_t smem_u32(const void* p) {
    return (uint32_t)__cvta_generic_to_shared(p);
}
__device__ __forceinline__ void ldsm_x4(uint32_t r[4], uint32_t addr) {
    asm volatile("ldmatrix.sync.aligned.m8n8.x4.shared.b16 {%0,%1,%2,%3}, [%4];"
        : "=r"(r[0]), "=r"(r[1]), "=r"(r[2]), "=r"(r[3]) : "r"(addr));
}
__device__ __forceinline__ void mma_bf16(float c[4], const uint32_t a[4],
                                         uint32_t b0, uint32_t b1) {
    asm volatile("mma.sync.aligned.m16n8k16.row.col.f32.bf16.bf16.f32 "
        "{%0,%1,%2,%3},{%4,%5,%6,%7},{%8,%9},{%0,%1,%2,%3};"
        : "+f"(c[0]), "+f"(c[1]), "+f"(c[2]), "+f"(c[3])
        : "r"(a[0]), "r"(a[1]), "r"(a[2]), "r"(a[3]), "r"(b0), "r"(b1));
}
__device__ __forceinline__ void mma_k8(float c[4], uint32_t a0, uint32_t a1,
                                       uint32_t b) {
    asm volatile("mma.sync.aligned.m16n8k8.row.col.f32.bf16.bf16.f32 "
        "{%0,%1,%2,%3},{%4,%5},{%6},{%0,%1,%2,%3};"
        : "+f"(c[0]), "+f"(c[1]), "+f"(c[2]), "+f"(c[3])
        : "r"(a0), "r"(a1), "r"(b));
}

// split 8 fp32 -> 8 bf16 hi + 8 bf16 lo (as uint4 each)
__device__ __forceinline__ void split8(const float4 a, const float4 b,
                                       uint4& hi, uint4& lo) {
    const float xs[8] = {a.x, a.y, a.z, a.w, b.x, b.y, b.z, b.w};
    __nv_bfloat16 hs[8], ls[8];
    #pragma unroll
    for (int i = 0; i < 8; ++i) {
        hs[i] = __float2bfloat16(xs[i]);
        ls[i] = __float2bfloat16(xs[i] - __bfloat162float(hs[i]));
    }
    hi = *(uint4*)hs;
    lo = *(uint4*)ls;
}

// ---------------- Pass A1: split-K tensor-core QKV projection ----------------
// grid (32, 3, 8): kz chunk of K=256 (8 stages). fp32 inputs, in-register
// hi/lo split (no separate convert kernels). fp32 partials to g_part.
#define PSTR 40
__global__ __launch_bounds__(256) void proj_mma(
    const float* __restrict__ X,
    const float* __restrict__ Wq,
    const float* __restrict__ Wk,
    const float* __restrict__ Wv)
{
    __shared__ __nv_bfloat16 sAh[2][64 * PSTR], sAl[2][64 * PSTR];
    __shared__ __nv_bfloat16 sBh[2][64 * PSTR], sBl[2][64 * PSTR];

    const int m0 = blockIdx.x * 64;
    const int n0 = blockIdx.y * 64;
    const int kz = blockIdx.z;
    const size_t kbase = (size_t)kz * 256;
    const int t  = threadIdx.x;
    const int w  = t >> 5, lane = t & 31;
    const int wm = (w & 3) * 16;
    const int wn = (w >> 2) * 32;

    const int lrow = t >> 2;
    const int lcol = (t & 3) * 8;
    const float* arow = X + (size_t)(m0 + lrow) * DMODEL + kbase + lcol;
    const int gn = n0 + lrow;
    const float* brow;
    if (gn < 128)      brow = Wq + (size_t)gn * DMODEL;
    else if (gn < 160) brow = Wk + (size_t)(gn - 128) * DMODEL;
    else               brow = Wv + (size_t)(gn - 160) * DMODEL;
    brow += kbase + lcol;
    const int sidx = lrow * PSTR + lcol;

    const int seg = lane >> 3, lr8 = lane & 7;
    const int a_r = wm + (seg & 1) * 8 + lr8;
    const int a_c0 = (seg >> 1) * 8;

    float acc[4][4] = {};

    float4 pa0 = *(const float4*)(arow);
    float4 pa1 = *(const float4*)(arow + 4);
    float4 pb0 = *(const float4*)(brow);
    float4 pb1 = *(const float4*)(brow + 4);

    for (int stage = 0; stage < 8; ++stage) {
        const int buf = stage & 1;
        uint4 ahi, alo, bhi, blo;
        split8(pa0, pa1, ahi, alo);
        split8(pb0, pb1, bhi, blo);
        __syncthreads();
        *(uint4*)&sAh[buf][sidx] = ahi;
        *(uint4*)&sAl[buf][sidx] = alo;
        *(uint4*)&sBh[buf][sidx] = bhi;
        *(uint4*)&sBl[buf][sidx] = blo;
        __syncthreads();
        if (stage + 1 < 8) {
            const int koff = (stage + 1) * 32;
            pa0 = *(const float4*)(arow + koff);
            pa1 = *(const float4*)(arow + koff + 4);
            pb0 = *(const float4*)(brow + koff);
            pb1 = *(const float4*)(brow + koff + 4);
        }
        #pragma unroll
        for (int ks = 0; ks < 32; ks += 16) {
            uint32_t ah[4], al[4];
            {
                const int ac = ks + a_c0;
                ldsm_x4(ah, smem_u32(&sAh[buf][a_r * PSTR + ac]));
                ldsm_x4(al, smem_u32(&sAl[buf][a_r * PSTR + ac]));
            }
            #pragma unroll
            for (int nb = 0; nb < 32; nb += 16) {
                const int b_r = wn + nb + (seg >> 1) * 8 + lr8;
                const int b_c = ks + (seg & 1) * 8;
                uint32_t bh[4], bl[4];
                ldsm_x4(bh, smem_u32(&sBh[buf][b_r * PSTR + b_c]));
                ldsm_x4(bl, smem_u32(&sBl[buf][b_r * PSTR + b_c]));
                const int nt = nb >> 3;
                mma_bf16(acc[nt],     ah, bh[0], bh[1]);
                mma_bf16(acc[nt],     ah, bl[0], bl[1]);
                mma_bf16(acc[nt],     al, bh[0], bh[1]);
                mma_bf16(acc[nt + 1], ah, bh[2], bh[3]);
                mma_bf16(acc[nt + 1], ah, bl[2], bl[3]);
                mma_bf16(acc[nt + 1], al, bh[2], bh[3]);
            }
        }
    }

    const int group = lane >> 2, tg = lane & 3;
    #pragma unroll
    for (int nt = 0; nt < 4; ++nt) {
        const int n = n0 + wn + nt * 8 + tg * 2;
        const int m = m0 + wm + group;
        #pragma unroll
        for (int e = 0; e < 4; ++e) {
            const int mm = m + (e >> 1) * 8;
            const int nn = n + (e & 1);
            g_part[((size_t)kz * SEQ + mm) * 192 + nn] = acc[nt][e];
        }
    }
}

// ---------------- Pass A2: reduce partials + activations + hi/lo split ----------------
__global__ __launch_bounds__(256) void proj_act(const float* __restrict__ tau)
{
    const int idx = blockIdx.x * 256 + threadIdx.x;
    const float inv_tau = 1.0f / tau[0];
    float s = 0.0f;
    #pragma unroll
    for (int p = 0; p < 8; ++p) s += g_part[(size_t)p * (SEQ * 192) + idx];
    const int m = idx / 192;
    const int n = idx - m * 192;
    const float x = s * inv_tau;
    if (n < 160) {
        const float tv = tanhf(x);
        const __nv_bfloat16 th = __float2bfloat16(tv);
        const __nv_bfloat16 tl = __float2bfloat16(tv - __bfloat162float(th));
        if (n < 128) { g_qh[m * 128 + n] = th; g_ql[m * 128 + n] = tl; }
        else { g_kh[m * 32 + (n - 128)] = th; g_kl[m * 32 + (n - 128)] = tl; }
    } else {
        g_v[m * 32 + (n - 160)] = 1.0f / (1.0f + expf(-x));
    }
}

// ---------------- Pass B: split-K suffix attention (frozen from R16) ----------------
__global__ __launch_bounds__(256, 3) void attn_kernel(const float* __restrict__ tau)
{
    extern __shared__ float smem[];
    const uint32_t* qh32 = (const uint32_t*)(smem + QHS_OFF);
    const uint32_t* ql32 = (const uint32_t*)(smem + QLS_OFF);
    float* vsb = smem + VS_OFF;
    float* G   = smem + G_OFF;

    const int kz = blockIdx.x;
    const int qb = blockIdx.y;
    const int h  = blockIdx.z;
    const int q0 = qb * 64;
    const int c  = h >> 2;
    const int t  = threadIdx.x;
    const int kb0 = kz * 4;

    if (kb0 > qb) {
        if (t < 64) {
            const int qg = q0 + t;
            g_pl[((size_t)kz * SEQ + qg) * 16 + h] = 0.0f;
            float* pa = &g_pacc[((size_t)kz * SEQ + qg) * 128 + h * 8];
            #pragma unroll
            for (int d = 0; d < 8; ++d) pa[d] = 0.0f;
        }
        return;
    }
    const int kb1 = (kb0 + 3 < qb) ? kb0 + 3 : qb;

    const int w  = t >> 5, lane = t & 31;
    const float inv_tau = 1.0f / tau[0];
    const float scale   = 0.0625f * inv_tau;

    if (t < 192) {
        const int r = t >> 1, half = t & 1;
        const int gq = q0 - 31 + r;
        uint4 v4 = make_uint4(0u, 0u, 0u, 0u);
        const __nv_bfloat16* src = half ? g_ql : g_qh;
        if (gq >= 0 && gq < SEQ) v4 = *(const uint4*)&src[gq * 128 + h * 8];
        float* dst = smem + (half ? QLS_OFF : QHS_OFF);
        *(uint4*)&dst[r * 4] = v4;
    }

    const int a  = t >> 2;
    const int jq = t & 3;
    const int qg = q0 + a;
    const float bias_r = inv_tau / (float)(qg + 1);

    float l_run = 0.0f;
    float acc[8];
    #pragma unroll
    for (int d = 0; d < 8; ++d) acc[d] = 0.0f;

    const int fr = lane >> 2, fq = lane & 3;
    const int fc = fq * 2;

    const int lr = t >> 1, lhalf = t & 1;
    const int lu = t - 192;

    {
        const int k0 = kb0 * 64;
        if (t < 192) {
            const int gk = k0 - 31 + lr;
            uint4 v4 = make_uint4(0u, 0u, 0u, 0u);
            const __nv_bfloat16* src = lhalf ? g_kl : g_kh;
            if (gk >= 0 && gk < SEQ) v4 = *(const uint4*)&src[gk * 32 + c * 8];
            float* dst = smem + (lhalf ? KLS_OFF : KHS_OFF);
            *(uint4*)&dst[lr * 4] = v4;
        } else {
            #pragma unroll
            for (int rep = 0; rep < 2; ++rep) {
                const int idx = lu * 2 + rep;
                const int r = idx >> 1, half = idx & 1;
                const int gk = k0 + r + 1;
                float4 v4 = make_float4(0.f, 0.f, 0.f, 0.f);
                if (gk < SEQ) v4 = *(const float4*)&g_v[gk * 32 + c * 8 + half * 4];
                *(float4*)&vsb[r * 8 + half * 4] = v4;
            }
        }
    }

    for (int kb = kb0; kb <= kb1; ++kb) {
        const int k0 = kb * 64;
        const int buf = (kb - kb0) & 1;
        const uint32_t* kh32 = (const uint32_t*)(smem + KHS_OFF + buf * 384);
        const uint32_t* kl32 = (const uint32_t*)(smem + KLS_OFF + buf * 384);
        const float* vsm = vsb + buf * 512;
        __syncthreads();

        #pragma unroll
        for (int k9 = 0; k9 < 9; ++k9) {
            const int p  = w + (k9 << 3);
            const int mt = p / 12;
            const int nt = p - mt * 12;
            const int ai = (mt * 16 + fr) * 4 + fq;
            const uint32_t ah0 = qh32[ai],      ah1 = qh32[ai + 32];
            const uint32_t al0 = ql32[ai],      al1 = ql32[ai + 32];
            const int bi = (nt * 8 + fr) * 4 + fq;
            const uint32_t bh = kh32[bi], bl = kl32[bi];
            float cfr[4] = {0.f, 0.f, 0.f, 0.f};
            mma_k8(cfr, ah0, ah1, bh);
            mma_k8(cfr, ah0, ah1, bl);
            mma_k8(cfr, al0, al1, bh);
            float* gp = &G[(mt * 16 + fr) * GSTR + nt * 8 + fc];
            gp[0] = cfr[0]; gp[1] = cfr[1];
            gp[8 * GSTR] = cfr[2]; gp[8 * GSTR + 1] = cfr[3];
        }
        __syncthreads();

        if (t < 191) {
            const int dlt = t - 95;
            const int ad  = dlt < 0 ? -dlt : dlt;
            const int L   = 96 - ad;
            int off = (dlt > 0) ? dlt * GSTR : -dlt;
            float carry = 0.0f;
            int s = 0;
            for (; s + 4 <= L; s += 4) {
                const float e0 = G[off];
                const float e1 = G[off + (GSTR + 1)];
                const float e2 = G[off + 2 * (GSTR + 1)];
                const float e3 = G[off + 3 * (GSTR + 1)];
                const float c0 = carry + e0;
                const float c1 = c0 + e1;
                const float c2 = c1 + e2;
                const float c3 = c2 + e3;
                G[off] = c0;
                G[off + (GSTR + 1)]     = c1;
                G[off + 2 * (GSTR + 1)] = c2;
                G[off + 3 * (GSTR + 1)] = c3;
                carry = c3;
                off += 4 * (GSTR + 1);
            }
            for (; s < L; ++s) { carry += G[off]; G[off] = carry; off += GSTR + 1; }
        } else if (t >= 192 && kb < kb1) {
            const int nk0 = k0 + 64;
            #pragma unroll
            for (int rep = 0; rep < 2; ++rep) {
                const int idx = lu * 2 + rep;
                const int r = idx >> 1, half = idx & 1;
                const int gk = nk0 + r + 1;
                float4 v4 = make_float4(0.f, 0.f, 0.f, 0.f);
                if (gk < SEQ) v4 = *(const float4*)&g_v[gk * 32 + c * 8 + half * 4];
                *(float4*)&vsb[(buf ^ 1) * 512 + r * 8 + half * 4] = v4;
            }
        }
        __syncthreads();

        if (kb < kb1 && t < 192) {
            const int gk = k0 + 64 - 31 + lr;
            const __nv_bfloat16* src = lhalf ? g_kl : g_kh;
            const uint4 v4 = *(const uint4*)&src[gk * 32 + c * 8];
            float* dst = smem + (lhalf ? KLS_OFF : KHS_OFF) + (buf ^ 1) * 384;
            *(uint4*)&dst[lr * 4] = v4;
        }

        const int browH = (a + 31) * GSTR + 31;
        const int browL = (a - 1) * GSTR - 1;
        #pragma unroll
        for (int bb = 0; bb < 16; ++bb) {
            const int b  = (bb << 2) | jq;
            const int kg = k0 + b;
            if (kg < qg) {
                const float hi = G[browH + b];
                const float lo = (a > 0 && b > 0) ? G[browL + b] : 0.0f;
                const float s = (hi - lo) * scale + (float)kg * bias_r;
                const float e = __expf(s);
                l_run += e;
                const float4 v0 = *(const float4*)&vsm[b * 8];
                const float4 v1 = *(const float4*)&vsm[b * 8 + 4];
                acc[0] = fmaf(e, v0.x, acc[0]); acc[1] = fmaf(e, v0.y, acc[1]);
                acc[2] = fmaf(e, v0.z, acc[2]); acc[3] = fmaf(e, v0.w, acc[3]);
                acc[4] = fmaf(e, v1.x, acc[4]); acc[5] = fmaf(e, v1.y, acc[5]);
                acc[6] = fmaf(e, v1.z, acc[6]); acc[7] = fmaf(e, v1.w, acc[7]);
            }
        }
    }

    #pragma unroll
    for (int off = 1; off < 4; off <<= 1) {
        l_run += __shfl_xor_sync(0xffffffffu, l_run, off);
        #pragma unroll
        for (int d = 0; d < 8; ++d)
            acc[d] += __shfl_xor_sync(0xffffffffu, acc[d], off);
    }
    if (jq == 0) {
        g_pl[((size_t)kz * SEQ + qg) * 16 + h] = l_run;
        float* pa = &g_pacc[((size_t)kz * SEQ + qg) * 128 + h * 8];
        #pragma unroll
        for (int d = 0; d < 8; ++d) pa[d] = acc[d];
    }
}

// ---------------- Pass B2: merge attn partials, affine, bf16 split ----------------
__global__ __launch_bounds__(256) void attn_fin(
    const float* __restrict__ ve0,
    const float* __restrict__ ve1)
{
    const int idx = blockIdx.x * 256 + threadIdx.x;
    const int q = idx >> 7;
    const int f = idx & 127;
    const int h = f >> 3;
    float l = 0.0f, s = 0.0f;
    #pragma unroll
    for (int kz = 0; kz < 8; ++kz) {
        l += g_pl[((size_t)kz * SEQ + q) * 16 + h];
        s += g_pacc[((size_t)kz * SEQ + q) * 128 + f];
    }
    const float invl = (l > 0.0f) ? 1.0f / l : 0.0f;
    const float o = s * invl;
    const float fin = o * (ve1[f] - ve0[f]) + ve0[f];
    const __nv_bfloat16 fh = __float2bfloat16(fin);
    const __nv_bfloat16 fl = __float2bfloat16(fin - __bfloat162float(fh));
    g_oh[idx] = fh;
    g_ol[idx] = fl;
}

// ---------------- Pass C: output projection via MMA (K=128) ----------------
// Wo loaded fp32, split in-register (no convert_wo kernel).
__global__ __launch_bounds__(256) void out_mma(
    const float* __restrict__ Wo,
    float* __restrict__ out)
{
    __shared__ __nv_bfloat16 sAh[2][64 * PSTR], sAl[2][64 * PSTR];
    __shared__ __nv_bfloat16 sBh[2][64 * PSTR], sBl[2][64 * PSTR];

    const int m0 = blockIdx.x * 64;
    const int n0 = blockIdx.y * 64;
    const int t  = threadIdx.x;
    const int w  = t >> 5, lane = t & 31;
    const int wm = (w & 3) * 16;
    const int wn = (w >> 2) * 32;

    const int lrow = t >> 2;
    const int lcol = (t & 3) * 8;
    const size_t aoff0 = (size_t)(m0 + lrow) * 128 + lcol;
    const float* brow = Wo + (size_t)(n0 + lrow) * 128 + lcol;
    const int sidx = lrow * PSTR + lcol;

    const int seg = lane >> 3, lr8 = lane & 7;
    const int a_r = wm + (seg & 1) * 8 + lr8;
    const int a_c0 = (seg >> 1) * 8;

    float acc[4][4] = {};

    uint4 pah = *(const uint4*)&g_oh[aoff0];
    uint4 pal = *(const uint4*)&g_ol[aoff0];
    float4 pb0 = *(const float4*)(brow);
    float4 pb1 = *(const float4*)(brow + 4);

    for (int stage = 0; stage < 4; ++stage) {
        const int buf = stage & 1;
        uint4 bhi, blo;
        split8(pb0, pb1, bhi, blo);
        __syncthreads();
        *(uint4*)&sAh[buf][sidx] = pah;
        *(uint4*)&sAl[buf][sidx] = pal;
        *(uint4*)&sBh[buf][sidx] = bhi;
        *(uint4*)&sBl[buf][sidx] = blo;
        __syncthreads();
        if (stage + 1 < 4) {
            const int koff = (stage + 1) * 32;
            pah = *(const uint4*)&g_oh[aoff0 + koff];
            pal = *(const uint4*)&g_ol[aoff0 + koff];
            pb0 = *(const float4*)(brow + koff);
            pb1 = *(const float4*)(brow + koff + 4);
        }
        #pragma unroll
        for (int ks = 0; ks < 32; ks += 16) {
            uint32_t ah[4], al[4];
            {
                const int ac = ks + a_c0;
                ldsm_x4(ah, smem_u32(&sAh[buf][a_r * PSTR + ac]));
                ldsm_x4(al, smem_u32(&sAl[buf][a_r * PSTR + ac]));
            }
            #pragma unroll
            for (int nb = 0; nb < 32; nb += 16) {
                const int b_r = wn + nb + (seg >> 1) * 8 + lr8;
                const int b_c = ks + (seg & 1) * 8;
                uint32_t bh[4], bl[4];
                ldsm_x4(bh, smem_u32(&sBh[buf][b_r * PSTR + b_c]));
                ldsm_x4(bl, smem_u32(&sBl[buf][b_r * PSTR + b_c]));
                const int nt = nb >> 3;
                mma_bf16(acc[nt],     ah, bh[0], bh[1]);
                mma_bf16(acc[nt],     ah, bl[0], bl[1]);
                mma_bf16(acc[nt],     al, bh[0], bh[1]);
                mma_bf16(acc[nt + 1], ah, bh[2], bh[3]);
                mma_bf16(acc[nt + 1], ah, bl[2], bl[3]);
                mma_bf16(acc[nt + 1], al, bh[2], bh[3]);
            }
        }
    }

    const int group = lane >> 2, tg = lane & 3;
    #pragma unroll
    for (int nt = 0; nt < 4; ++nt) {
        const int n = n0 + wn + nt * 8 + tg * 2;
        const int m = m0 + wm + group;
        #pragma unroll
        for (int e = 0; e < 4; ++e) {
            const int mm = m + (e >> 1) * 8;
            const int nn = n + (e & 1);
            out[(size_t)mm * DMODEL + nn] = acc[nt][e];
        }
    }
}

// ---------------- launch ----------------
extern "C" void kernel_launch(void* const* d_in, const int* in_sizes, int n_in,
                              void* d_out, int out_size)
{
    const float* X   = (const float*)d_in[0];
    const float* Wq  = (const float*)d_in[1];
    const float* Wk  = (const float*)d_in[2];
    const float* Wv  = (const float*)d_in[3];
    const float* Wo  = (const float*)d_in[4];
    const float* ve0 = (const float*)d_in[5];
    const float* ve1 = (const float*)d_in[6];
    const float* tau = (const float*)d_in[7];
    float* out = (float*)d_out;
    (void)in_sizes; (void)n_in; (void)out_size;

    cudaFuncSetAttribute(attn_kernel,
                         cudaFuncAttributeMaxDynamicSharedMemorySize,
                         SMEM_FLOATS * (int)sizeof(float));

    proj_mma  <<<dim3(32, 3, 8), 256>>>(X, Wq, Wk, Wv);
    proj_act  <<<1536, 256>>>(tau);
    attn_kernel<<<dim3(8, 32, 16), 256, SMEM_FLOATS * sizeof(float)>>>(tau);
    attn_fin  <<<1024, 256>>>(ve0, ve1);
    out_mma   <<<dim3(32, 32), 256>>>(Wo, out);
}